// round 3
// baseline (speedup 1.0000x reference)
#include <cuda_runtime.h>

#define D_MODEL 768
#define NHEADS  12
#define DKH     64
#define SEQ     2048
#define BATCH   2
#define DFF     3072
#define MROWS   (BATCH*SEQ)          // 4096
#define BHTOT   (BATCH*NHEADS)      // 24
#define LN_EPS  1e-6f

// ---------------- scratch (static device memory, allowed) ----------------
__device__ __align__(16) float g_q   [BHTOT*SEQ*DKH];
__device__ __align__(16) float g_k   [BHTOT*SEQ*DKH];
__device__ __align__(16) float g_v   [BHTOT*SEQ*DKH];
__device__ __align__(16) float g_attn[MROWS*D_MODEL];
__device__ __align__(16) float g_res1[MROWS*D_MODEL];
__device__ __align__(16) float g_x1  [MROWS*D_MODEL];
__device__ __align__(16) float g_ff  [MROWS*DFF];
__device__ __align__(16) float g_res2[MROWS*D_MODEL];
__device__ __align__(16) unsigned char g_maskc[BATCH*SEQ];   // canonical 0/1 bytes

// ---------------- mask canonicalization (dtype auto-detect) ----------------
// Reference mask is bool (B,1,1,S) = 4096 elems. Harness delivers either
// int32 (one word per elem, value 0/1) or packed uint8. Detect: interpret
// the first 1024 words (4KB, safe under both layouts); if ANY word > 1 it
// must be packed uint8 (e.g. 0x00010100). Then expand to canonical bytes.
__global__ void mask_canon_kernel(const void* __restrict__ mraw)
{
    __shared__ int s_flag;
    const unsigned int* w = (const unsigned int*)mraw;
    if (threadIdx.x == 0) s_flag = 0;
    __syncthreads();
    int any = 0;
    for (int i = threadIdx.x; i < 1024; i += 256)
        if (w[i] > 1u) any = 1;
    if (any) atomicOr(&s_flag, 1);
    __syncthreads();
    const int is_u8 = s_flag;
    if (is_u8) {
        const unsigned char* mb = (const unsigned char*)mraw;
        for (int i = threadIdx.x; i < BATCH * SEQ; i += 256)
            g_maskc[i] = mb[i] ? 1 : 0;
    } else {
        const int* mi = (const int*)mraw;
        for (int i = threadIdx.x; i < BATCH * SEQ; i += 256)
            g_maskc[i] = mi[i] ? 1 : 0;
    }
}

// ---------------- packed f32x2 helpers ----------------
__device__ __forceinline__ unsigned long long pk2(float lo, float hi) {
    unsigned long long r;
    asm("mov.b64 %0, {%1,%2};" : "=l"(r) : "f"(lo), "f"(hi));
    return r;
}
__device__ __forceinline__ void upk2(unsigned long long v, float& lo, float& hi) {
    asm("mov.b64 {%0,%1}, %2;" : "=f"(lo), "=f"(hi) : "l"(v));
}
#define FMA2(d, a, b, c) asm("fma.rn.f32x2 %0, %1, %2, %3;" : "=l"(d) : "l"(a), "l"(b), "l"(c))

// ---------------- GEMM: C[m,n] = sum_k A[m,k]*W[n,k] (+epilogue) ----------------
enum { EPI_PLAIN = 0, EPI_RELU = 1, EPI_RES = 2, EPI_QKV = 3 };

template<int EPI>
__global__ __launch_bounds__(256, 2)
void gemm128(const float* __restrict__ A, const float* __restrict__ W,
             const float* __restrict__ bias, const float* __restrict__ res,
             float* __restrict__ out, int Kdim, int Ndim)
{
    __shared__ __align__(16) float As[8 * 128];
    __shared__ __align__(16) float Ws[8 * 128];

    const int tid = threadIdx.x;
    const int tx = tid & 15, ty = tid >> 4;
    const int m0 = blockIdx.x * 128, n0 = blockIdx.y * 128;
    const int lrow = tid >> 1;          // 0..127
    const int lc4  = (tid & 1) * 4;     // 0 or 4

    const float* Ap = A + (size_t)(m0 + lrow) * Kdim + lc4;
    const float* Wp = W + (size_t)(n0 + lrow) * Kdim + lc4;

    unsigned long long acc[8][4];
#pragma unroll
    for (int i = 0; i < 8; i++)
#pragma unroll
        for (int j = 0; j < 4; j++) acc[i][j] = 0ull;

    for (int k0 = 0; k0 < Kdim; k0 += 8) {
        float4 av = *(const float4*)(Ap + k0);
        float4 wv = *(const float4*)(Wp + k0);
        __syncthreads();
        As[(lc4 + 0) * 128 + lrow] = av.x;
        As[(lc4 + 1) * 128 + lrow] = av.y;
        As[(lc4 + 2) * 128 + lrow] = av.z;
        As[(lc4 + 3) * 128 + lrow] = av.w;
        Ws[(lc4 + 0) * 128 + lrow] = wv.x;
        Ws[(lc4 + 1) * 128 + lrow] = wv.y;
        Ws[(lc4 + 2) * 128 + lrow] = wv.z;
        Ws[(lc4 + 3) * 128 + lrow] = wv.w;
        __syncthreads();

#pragma unroll
        for (int kk = 0; kk < 8; kk++) {
            float4 a0 = *(const float4*)&As[kk * 128 + ty * 8];
            float4 a1 = *(const float4*)&As[kk * 128 + ty * 8 + 4];
            float4 w0 = *(const float4*)&Ws[kk * 128 + tx * 8];
            float4 w1 = *(const float4*)&Ws[kk * 128 + tx * 8 + 4];
            unsigned long long wp0 = pk2(w0.x, w0.y);
            unsigned long long wp1 = pk2(w0.z, w0.w);
            unsigned long long wp2 = pk2(w1.x, w1.y);
            unsigned long long wp3 = pk2(w1.z, w1.w);
            float aa[8] = {a0.x, a0.y, a0.z, a0.w, a1.x, a1.y, a1.z, a1.w};
#pragma unroll
            for (int i = 0; i < 8; i++) {
                unsigned long long ad = pk2(aa[i], aa[i]);
                FMA2(acc[i][0], ad, wp0, acc[i][0]);
                FMA2(acc[i][1], ad, wp1, acc[i][1]);
                FMA2(acc[i][2], ad, wp2, acc[i][2]);
                FMA2(acc[i][3], ad, wp3, acc[i][3]);
            }
        }
    }

#pragma unroll
    for (int i = 0; i < 8; i++) {
        int m = m0 + ty * 8 + i;
#pragma unroll
        for (int jp = 0; jp < 4; jp++) {
            float lo, hi;
            upk2(acc[i][jp], lo, hi);
            int n = n0 + tx * 8 + jp * 2;
            float v0 = lo + bias[n];
            float v1 = hi + bias[n + 1];
            if (EPI == EPI_RELU) { v0 = fmaxf(v0, 0.f); v1 = fmaxf(v1, 0.f); }
            if (EPI == EPI_RES) {
                v0 += res[(size_t)m * Ndim + n];
                v1 += res[(size_t)m * Ndim + n + 1];
            }
            if (EPI == EPI_QKV) {
                int b = m >> 11, s = m & (SEQ - 1);
                int h0 = n >> 6, d0 = n & 63;
                out[((size_t)(b * NHEADS + h0) * SEQ + s) * DKH + d0] = v0;
                int h1 = (n + 1) >> 6, d1 = (n + 1) & 63;
                out[((size_t)(b * NHEADS + h1) * SEQ + s) * DKH + d1] = v1;
            } else {
                out[(size_t)m * Ndim + n]     = v0;
                out[(size_t)m * Ndim + n + 1] = v1;
            }
        }
    }
}

// ---------------- Flash attention (fp32, BQ=64, BK=64, Dk=64) ----------------
__global__ __launch_bounds__(256)
void flash_attn(const float* __restrict__ Q, const float* __restrict__ K,
                const float* __restrict__ V, float* __restrict__ O)
{
    __shared__ __align__(16) float Qs[64 * 64];   // [d][q]  (transposed)
    __shared__ __align__(16) float KP[64 * 64];   // K: [d][k] then reused as P: [q][k]
    __shared__ __align__(16) float Vs[64 * 64];   // [k][d]  (natural)

    const int tid = threadIdx.x;
    const int tx = tid & 15, ty = tid >> 4;
    const int bh = blockIdx.y;
    const int b = bh / NHEADS;
    const int h = bh - b * NHEADS;
    const int q0 = blockIdx.x * 64;

    const float* Qb = Q + (size_t)bh * SEQ * DKH;
    const float* Kb = K + (size_t)bh * SEQ * DKH;
    const float* Vb = V + (size_t)bh * SEQ * DKH;
    const unsigned char* mrow = g_maskc + b * SEQ;

    // load Q tile transposed: Qs[d][q]
#pragma unroll
    for (int t = 0; t < 4; t++) {
        int f4 = tid + t * 256;
        int row = f4 >> 4, c4 = (f4 & 15) * 4;
        float4 qv = *(const float4*)(Qb + (size_t)(q0 + row) * DKH + c4);
        Qs[(c4 + 0) * 64 + row] = qv.x;
        Qs[(c4 + 1) * 64 + row] = qv.y;
        Qs[(c4 + 2) * 64 + row] = qv.z;
        Qs[(c4 + 3) * 64 + row] = qv.w;
    }

    float o[4][4];
    float mi[4], li[4];
#pragma unroll
    for (int i = 0; i < 4; i++) {
        mi[i] = -1e30f; li[i] = 0.f;
#pragma unroll
        for (int j = 0; j < 4; j++) o[i][j] = 0.f;
    }

    for (int k0 = 0; k0 < SEQ; k0 += 64) {
        // prefetch K/V tile into regs
        float4 kv[4], vv[4];
#pragma unroll
        for (int t = 0; t < 4; t++) {
            int f4 = tid + t * 256;
            int row = f4 >> 4, c4 = (f4 & 15) * 4;
            kv[t] = *(const float4*)(Kb + (size_t)(k0 + row) * DKH + c4);
            vv[t] = *(const float4*)(Vb + (size_t)(k0 + row) * DKH + c4);
        }
        __syncthreads();   // previous iteration done with KP/Vs
#pragma unroll
        for (int t = 0; t < 4; t++) {
            int f4 = tid + t * 256;
            int row = f4 >> 4, c4 = (f4 & 15) * 4;
            KP[(c4 + 0) * 64 + row] = kv[t].x;   // K transposed [d][k]
            KP[(c4 + 1) * 64 + row] = kv[t].y;
            KP[(c4 + 2) * 64 + row] = kv[t].z;
            KP[(c4 + 3) * 64 + row] = kv[t].w;
            *(float4*)&Vs[row * 64 + c4] = vv[t];
        }
        __syncthreads();

        // S = Q @ K^T  (4x4 per thread)
        float s[4][4];
#pragma unroll
        for (int i = 0; i < 4; i++)
#pragma unroll
            for (int j = 0; j < 4; j++) s[i][j] = 0.f;
#pragma unroll 8
        for (int d = 0; d < 64; d++) {
            float4 a = *(const float4*)&Qs[d * 64 + ty * 4];
            float4 bb = *(const float4*)&KP[d * 64 + tx * 4];
            float aa[4] = {a.x, a.y, a.z, a.w};
            float bv[4] = {bb.x, bb.y, bb.z, bb.w};
#pragma unroll
            for (int i = 0; i < 4; i++)
#pragma unroll
                for (int j = 0; j < 4; j++) s[i][j] += aa[i] * bv[j];
        }

        unsigned int mu = *(const unsigned int*)(mrow + k0 + tx * 4);
        float ps[4][4];
#pragma unroll
        for (int i = 0; i < 4; i++) {
            float sv[4];
#pragma unroll
            for (int j = 0; j < 4; j++) {
                float x = s[i][j] * 0.125f;
                if ((mu >> (8 * j)) & 0xffu) x = -1e9f;
                sv[j] = x;
            }
            float rmax = fmaxf(fmaxf(sv[0], sv[1]), fmaxf(sv[2], sv[3]));
#pragma unroll
            for (int off = 8; off >= 1; off >>= 1)
                rmax = fmaxf(rmax, __shfl_xor_sync(0xffffffffu, rmax, off));
            float mnew = fmaxf(mi[i], rmax);
            float rsum = 0.f;
#pragma unroll
            for (int j = 0; j < 4; j++) {
                float p = __expf(sv[j] - mnew);
                ps[i][j] = p;
                rsum += p;
            }
#pragma unroll
            for (int off = 8; off >= 1; off >>= 1)
                rsum += __shfl_xor_sync(0xffffffffu, rsum, off);
            float fac = __expf(mi[i] - mnew);
            li[i] = li[i] * fac + rsum;
            mi[i] = mnew;
#pragma unroll
            for (int j = 0; j < 4; j++) o[i][j] *= fac;
        }

        __syncthreads();   // everyone done reading KP as K
        // store P natural: KP[q][k]
#pragma unroll
        for (int i = 0; i < 4; i++)
#pragma unroll
            for (int j = 0; j < 4; j++)
                KP[(ty * 4 + i) * 64 + tx * 4 + j] = ps[i][j];
        __syncthreads();

        // O += P @ V
#pragma unroll 4
        for (int jq = 0; jq < 16; jq++) {
            float4 p0 = *(const float4*)&KP[(ty * 4 + 0) * 64 + jq * 4];
            float4 p1 = *(const float4*)&KP[(ty * 4 + 1) * 64 + jq * 4];
            float4 p2 = *(const float4*)&KP[(ty * 4 + 2) * 64 + jq * 4];
            float4 p3 = *(const float4*)&KP[(ty * 4 + 3) * 64 + jq * 4];
            float pm[4][4] = {{p0.x, p0.y, p0.z, p0.w},
                              {p1.x, p1.y, p1.z, p1.w},
                              {p2.x, p2.y, p2.z, p2.w},
                              {p3.x, p3.y, p3.z, p3.w}};
#pragma unroll
            for (int jj = 0; jj < 4; jj++) {
                float4 v4 = *(const float4*)&Vs[(jq * 4 + jj) * 64 + tx * 4];
                float vb[4] = {v4.x, v4.y, v4.z, v4.w};
#pragma unroll
                for (int i = 0; i < 4; i++)
#pragma unroll
                    for (int c = 0; c < 4; c++)
                        o[i][c] += pm[i][jj] * vb[c];
            }
        }
    }

    // write O: [b, s, h, dk] == [m, h*64+dk]
#pragma unroll
    for (int i = 0; i < 4; i++) {
        float inv = 1.f / li[i];
        int gr = q0 + ty * 4 + i;
        size_t base = ((size_t)(b * SEQ + gr)) * D_MODEL + h * DKH + tx * 4;
#pragma unroll
        for (int j = 0; j < 4; j++) O[base + j] = o[i][j] * inv;
    }
}

// ---------------- LayerNorm (torch semantics: ddof=1, /(std+eps)) ----------------
__global__ __launch_bounds__(256)
void layernorm_kernel(const float* __restrict__ in, const float* __restrict__ gamma,
                      const float* __restrict__ beta, float* __restrict__ out)
{
    __shared__ float red[32];
    __shared__ float bc[2];
    const int row = blockIdx.x;
    const int tid = threadIdx.x;
    const int lane = tid & 31, wid = tid >> 5;

    float v[3];
    float s1 = 0.f;
#pragma unroll
    for (int t = 0; t < 3; t++) {
        v[t] = in[(size_t)row * D_MODEL + tid + t * 256];
        s1 += v[t];
    }
#pragma unroll
    for (int off = 16; off >= 1; off >>= 1) s1 += __shfl_xor_sync(0xffffffffu, s1, off);
    if (lane == 0) red[wid] = s1;
    __syncthreads();
    if (tid == 0) {
        float acc = 0.f;
        for (int w = 0; w < 8; w++) acc += red[w];
        bc[0] = acc / (float)D_MODEL;
    }
    __syncthreads();
    float mean = bc[0];

    float s2 = 0.f;
#pragma unroll
    for (int t = 0; t < 3; t++) {
        float d = v[t] - mean;
        s2 += d * d;
    }
#pragma unroll
    for (int off = 16; off >= 1; off >>= 1) s2 += __shfl_xor_sync(0xffffffffu, s2, off);
    if (lane == 0) red[wid] = s2;
    __syncthreads();
    if (tid == 0) {
        float acc = 0.f;
        for (int w = 0; w < 8; w++) acc += red[w];
        float var = acc / (float)(D_MODEL - 1);
        bc[1] = 1.f / (sqrtf(var) + LN_EPS);
    }
    __syncthreads();
    float inv = bc[1];

#pragma unroll
    for (int t = 0; t < 3; t++) {
        int c = tid + t * 256;
        out[(size_t)row * D_MODEL + c] = gamma[c] * (v[t] - mean) * inv + beta[c];
    }
}

// ---------------- launch ----------------
extern "C" void kernel_launch(void* const* d_in, const int* in_sizes, int n_in,
                              void* d_out, int out_size)
{
    const float* x  = (const float*)d_in[0];
    const void*  mraw = (const void*)d_in[1];
    const float* wq = (const float*)d_in[2];
    const float* bq = (const float*)d_in[3];
    const float* wk = (const float*)d_in[4];
    const float* bk = (const float*)d_in[5];
    const float* wv = (const float*)d_in[6];
    const float* bv = (const float*)d_in[7];
    const float* wo = (const float*)d_in[8];
    const float* bo = (const float*)d_in[9];
    const float* w1 = (const float*)d_in[10];
    const float* b1 = (const float*)d_in[11];
    const float* w2 = (const float*)d_in[12];
    const float* b2 = (const float*)d_in[13];
    const float* g1 = (const float*)d_in[14];
    const float* be1 = (const float*)d_in[15];
    const float* g2 = (const float*)d_in[16];
    const float* be2 = (const float*)d_in[17];
    float* outp = (float*)d_out;

    float *q, *k, *v, *attn, *res1, *x1, *ff, *res2;
    cudaGetSymbolAddress((void**)&q,    g_q);
    cudaGetSymbolAddress((void**)&k,    g_k);
    cudaGetSymbolAddress((void**)&v,    g_v);
    cudaGetSymbolAddress((void**)&attn, g_attn);
    cudaGetSymbolAddress((void**)&res1, g_res1);
    cudaGetSymbolAddress((void**)&x1,   g_x1);
    cudaGetSymbolAddress((void**)&ff,   g_ff);
    cudaGetSymbolAddress((void**)&res2, g_res2);

    dim3 blk(256);
    dim3 gP(MROWS / 128, D_MODEL / 128);   // (32, 6)
    dim3 gF1(MROWS / 128, DFF / 128);      // (32, 24)

    // canonicalize mask (dtype auto-detect: int32 vs uint8)
    mask_canon_kernel<<<1, 256>>>(mraw);

    // QKV projections (scatter into [b,h,s,dk])
    gemm128<EPI_QKV><<<gP, blk>>>(x, wq, bq, nullptr, q, D_MODEL, D_MODEL);
    gemm128<EPI_QKV><<<gP, blk>>>(x, wk, bk, nullptr, k, D_MODEL, D_MODEL);
    gemm128<EPI_QKV><<<gP, blk>>>(x, wv, bv, nullptr, v, D_MODEL, D_MODEL);

    // attention
    flash_attn<<<dim3(SEQ / 64, BHTOT), blk>>>(q, k, v, attn);

    // output projection + residual, LN1
    gemm128<EPI_RES><<<gP, blk>>>(attn, wo, bo, x, res1, D_MODEL, D_MODEL);
    layernorm_kernel<<<MROWS, blk>>>(res1, g1, be1, x1);

    // FFN
    gemm128<EPI_RELU><<<gF1, blk>>>(x1, w1, b1, nullptr, ff, D_MODEL, DFF);
    gemm128<EPI_RES><<<gP, blk>>>(ff, w2, b2, x1, res2, DFF, D_MODEL);
    layernorm_kernel<<<MROWS, blk>>>(res2, g2, be2, outp);
}

// round 6
// speedup vs baseline: 3.8427x; 3.8427x over previous
#include <cuda_runtime.h>
#include <cuda_bf16.h>

#define D_MODEL 768
#define NHEADS  12
#define DKH     64
#define SEQ     2048
#define BATCH   2
#define DFF     3072
#define MROWS   (BATCH*SEQ)          // 4096
#define BHTOT   (BATCH*NHEADS)       // 24
#define LN_EPS  1e-6f

typedef __nv_bfloat16 bf16;
typedef __nv_bfloat162 bf162;

// ---------------- scratch (static device memory, allowed) ----------------
__device__ __align__(16) bf16 g_xh [MROWS*D_MODEL];
__device__ __align__(16) bf16 g_xl [MROWS*D_MODEL];
__device__ __align__(16) bf16 g_wqh[D_MODEL*D_MODEL];
__device__ __align__(16) bf16 g_wql[D_MODEL*D_MODEL];
__device__ __align__(16) bf16 g_wkh[D_MODEL*D_MODEL];
__device__ __align__(16) bf16 g_wkl[D_MODEL*D_MODEL];
__device__ __align__(16) bf16 g_wvh[D_MODEL*D_MODEL];
__device__ __align__(16) bf16 g_wvl[D_MODEL*D_MODEL];
__device__ __align__(16) bf16 g_woh[D_MODEL*D_MODEL];
__device__ __align__(16) bf16 g_wol[D_MODEL*D_MODEL];
__device__ __align__(16) bf16 g_w1h[DFF*D_MODEL];
__device__ __align__(16) bf16 g_w1l[DFF*D_MODEL];
__device__ __align__(16) bf16 g_w2h[D_MODEL*DFF];
__device__ __align__(16) bf16 g_w2l[D_MODEL*DFF];
__device__ __align__(16) bf16 g_qh [BHTOT*SEQ*DKH];
__device__ __align__(16) bf16 g_ql [BHTOT*SEQ*DKH];
__device__ __align__(16) bf16 g_kh [BHTOT*SEQ*DKH];
__device__ __align__(16) bf16 g_kl [BHTOT*SEQ*DKH];
__device__ __align__(16) bf16 g_vh [BHTOT*SEQ*DKH];
__device__ __align__(16) bf16 g_vl [BHTOT*SEQ*DKH];
__device__ __align__(16) bf16 g_ah [MROWS*D_MODEL];
__device__ __align__(16) bf16 g_al [MROWS*D_MODEL];
__device__ __align__(16) bf16 g_ffh[MROWS*DFF];
__device__ __align__(16) bf16 g_ffl[MROWS*DFF];
__device__ __align__(16) bf16 g_x1h[MROWS*D_MODEL];
__device__ __align__(16) bf16 g_x1l[MROWS*D_MODEL];
__device__ __align__(16) float g_res1[MROWS*D_MODEL];
__device__ __align__(16) float g_x1 [MROWS*D_MODEL];
__device__ __align__(16) float g_res2[MROWS*D_MODEL];
__device__ __align__(16) float g_maskf[BATCH*SEQ];   // 1.0 = masked, 0.0 = keep

// ---------------- asm helpers ----------------
__device__ __forceinline__ void ldsm4(unsigned* r, unsigned addr) {
    asm volatile("ldmatrix.sync.aligned.m8n8.x4.shared.b16 {%0,%1,%2,%3}, [%4];"
        : "=r"(r[0]), "=r"(r[1]), "=r"(r[2]), "=r"(r[3]) : "r"(addr));
}
__device__ __forceinline__ void ldsm4t(unsigned* r, unsigned addr) {
    asm volatile("ldmatrix.sync.aligned.m8n8.x4.trans.shared.b16 {%0,%1,%2,%3}, [%4];"
        : "=r"(r[0]), "=r"(r[1]), "=r"(r[2]), "=r"(r[3]) : "r"(addr));
}
__device__ __forceinline__ void mma16816(float* c, const unsigned* a, unsigned b0, unsigned b1) {
    asm volatile("mma.sync.aligned.m16n8k16.row.col.f32.bf16.bf16.f32 "
        "{%0,%1,%2,%3}, {%4,%5,%6,%7}, {%8,%9}, {%0,%1,%2,%3};"
        : "+f"(c[0]), "+f"(c[1]), "+f"(c[2]), "+f"(c[3])
        : "r"(a[0]), "r"(a[1]), "r"(a[2]), "r"(a[3]), "r"(b0), "r"(b1));
}
__device__ __forceinline__ void cp16(unsigned saddr, const void* gptr) {
    asm volatile("cp.async.ca.shared.global [%0], [%1], 16;" :: "r"(saddr), "l"(gptr));
}
__device__ __forceinline__ void cp_commit() { asm volatile("cp.async.commit_group;"); }
__device__ __forceinline__ void cp_wait1() { asm volatile("cp.async.wait_group 1;"); }
__device__ __forceinline__ void cp_wait0() { asm volatile("cp.async.wait_group 0;"); }

// split a pair of fp32 into packed bf16 hi and lo parts
__device__ __forceinline__ void split2(float e0, float e1, unsigned& h2, unsigned& l2) {
    bf162 h = __floats2bfloat162_rn(e0, e1);
    h2 = reinterpret_cast<unsigned&>(h);
    float f0 = __bfloat162float(h.x);
    float f1 = __bfloat162float(h.y);
    bf162 l = __floats2bfloat162_rn(e0 - f0, e1 - f1);
    l2 = reinterpret_cast<unsigned&>(l);
}

// ---------------- mask canonicalization → float selector ----------------
__global__ void mask_canon_kernel(const void* __restrict__ mraw)
{
    __shared__ int s_flag;
    const unsigned int* w = (const unsigned int*)mraw;
    if (threadIdx.x == 0) s_flag = 0;
    __syncthreads();
    int any = 0;
    for (int i = threadIdx.x; i < 1024; i += 256)
        if (w[i] > 1u) any = 1;
    if (any) atomicOr(&s_flag, 1);
    __syncthreads();
    if (s_flag) {
        const unsigned char* mb = (const unsigned char*)mraw;
        for (int i = threadIdx.x; i < BATCH * SEQ; i += 256)
            g_maskf[i] = mb[i] ? 1.0f : 0.0f;
    } else {
        const int* mi = (const int*)mraw;
        for (int i = threadIdx.x; i < BATCH * SEQ; i += 256)
            g_maskf[i] = mi[i] ? 1.0f : 0.0f;
    }
}

// ---------------- fp32 -> bf16 hi/lo split ----------------
__global__ void cvt_split(const float* __restrict__ s, bf16* __restrict__ h,
                          bf16* __restrict__ l, int n)
{
    int i = (blockIdx.x * 256 + threadIdx.x) * 4;
    if (i >= n) return;
    float4 v = *(const float4*)(s + i);
    unsigned h01, l01, h23, l23;
    split2(v.x, v.y, h01, l01);
    split2(v.z, v.w, h23, l23);
    *(unsigned*)(h + i)     = h01;
    *(unsigned*)(h + i + 2) = h23;
    *(unsigned*)(l + i)     = l01;
    *(unsigned*)(l + i + 2) = l23;
}

// ---------------- tensor-core GEMM: C[m,n] = sum_k A[m,k]*W[n,k] ----------------
// block 128x128, ktile 32, 8 warps (warp tile 32m x 64n), bf16-split 3-mma.
enum { EPI_QKV = 0, EPI_ORES = 1, EPI_FF1 = 2, EPI_FF2 = 3 };

#define GSM_BUF 40960   // 4 arrays of 128*40 bf16 (80B padded rows)

template<int EPI>
__global__ __launch_bounds__(256, 2)
void gemm_mma(const bf16* __restrict__ Ah, const bf16* __restrict__ Al,
              const bf16* __restrict__ Wh, const bf16* __restrict__ Wl,
              const float* __restrict__ bias, const float* __restrict__ res,
              float* __restrict__ outF, bf16* __restrict__ outH, bf16* __restrict__ outL,
              int Kdim, int Ndim)
{
    extern __shared__ char smem[];
    const unsigned sb = (unsigned)__cvta_generic_to_shared(smem);
    const int tid = threadIdx.x, lane = tid & 31, warp = tid >> 5;
    const int wm = warp & 3, wn = warp >> 2;
    const int m0 = blockIdx.x * 128, n0 = blockIdx.y * 128;

    const int lr = tid >> 1;          // 0..127
    const int lc = (tid & 1) * 2;     // chunk base 0 or 2
    const bf16* gAh = Ah + (size_t)(m0 + lr) * Kdim + lc * 8;
    const bf16* gAl = Al + (size_t)(m0 + lr) * Kdim + lc * 8;
    const bf16* gWh = Wh + (size_t)(n0 + lr) * Kdim + lc * 8;
    const bf16* gWl = Wl + (size_t)(n0 + lr) * Kdim + lc * 8;
    const unsigned st = lr * 80 + lc * 16;

    float acc[2][8][4] = {};

    const int nk = Kdim / 32;

    auto issue = [&](int kt, int buf) {
        unsigned b = sb + buf * GSM_BUF;
        int ke = kt * 32;
#pragma unroll
        for (int c = 0; c < 2; c++) {
            cp16(b +         st + c * 16, gAh + ke + c * 8);
            cp16(b + 10240 + st + c * 16, gAl + ke + c * 8);
            cp16(b + 20480 + st + c * 16, gWh + ke + c * 8);
            cp16(b + 30720 + st + c * 16, gWl + ke + c * 8);
        }
        cp_commit();
    };

    issue(0, 0);
    for (int kt = 0; kt < nk; kt++) {
        int buf = kt & 1;
        if (kt + 1 < nk) { issue(kt + 1, buf ^ 1); cp_wait1(); }
        else             { cp_wait0(); }
        __syncthreads();

        unsigned b = sb + buf * GSM_BUF;
        const unsigned ar = lane & 15;
#pragma unroll
        for (int ks = 0; ks < 2; ks++) {
            const unsigned ac = ks * 2 + (lane >> 4);
            unsigned ah[2][4], al[2][4];
#pragma unroll
            for (int mi = 0; mi < 2; mi++) {
                unsigned addr = b + (wm * 32 + mi * 16 + ar) * 80 + ac * 16;
                ldsm4(ah[mi], addr);
                ldsm4(al[mi], addr + 10240);
            }
#pragma unroll
            for (int ni2 = 0; ni2 < 4; ni2++) {
                unsigned bh[4], bl[4];
                unsigned addr = b + 20480 + (wn * 64 + ni2 * 16 + ar) * 80 + ac * 16;
                ldsm4(bh, addr);
                ldsm4(bl, addr + 10240);
#pragma unroll
                for (int mi = 0; mi < 2; mi++) {
                    mma16816(acc[mi][ni2 * 2],     ah[mi], bh[0], bh[2]);
                    mma16816(acc[mi][ni2 * 2 + 1], ah[mi], bh[1], bh[3]);
                    mma16816(acc[mi][ni2 * 2],     ah[mi], bl[0], bl[2]);
                    mma16816(acc[mi][ni2 * 2 + 1], ah[mi], bl[1], bl[3]);
                    mma16816(acc[mi][ni2 * 2],     al[mi], bh[0], bh[2]);
                    mma16816(acc[mi][ni2 * 2 + 1], al[mi], bh[1], bh[3]);
                }
            }
        }
        __syncthreads();
    }

    // epilogue
#pragma unroll
    for (int mi = 0; mi < 2; mi++)
#pragma unroll
    for (int rr = 0; rr < 2; rr++) {
        int m = m0 + wm * 32 + mi * 16 + (lane >> 2) + rr * 8;
#pragma unroll
        for (int ni = 0; ni < 8; ni++) {
            int n = n0 + wn * 64 + ni * 8 + (lane & 3) * 2;
            float v0 = acc[mi][ni][rr * 2 + 0] + bias[n];
            float v1 = acc[mi][ni][rr * 2 + 1] + bias[n + 1];
            if (EPI == EPI_QKV) {
                int b_ = m >> 11, s_ = m & (SEQ - 1);
                int h_ = n >> 6, d_ = n & 63;
                size_t idx = ((size_t)(b_ * NHEADS + h_) * SEQ + s_) * DKH + d_;
                unsigned h2, l2;
                split2(v0, v1, h2, l2);
                *(unsigned*)(outH + idx) = h2;
                *(unsigned*)(outL + idx) = l2;
            } else if (EPI == EPI_ORES || EPI == EPI_FF2) {
                v0 += res[(size_t)m * Ndim + n];
                v1 += res[(size_t)m * Ndim + n + 1];
                outF[(size_t)m * Ndim + n]     = v0;
                outF[(size_t)m * Ndim + n + 1] = v1;
            } else { // EPI_FF1: relu + bf16 split
                v0 = fmaxf(v0, 0.f);
                v1 = fmaxf(v1, 0.f);
                unsigned h2, l2;
                split2(v0, v1, h2, l2);
                size_t idx = (size_t)m * Ndim + n;
                *(unsigned*)(outH + idx) = h2;
                *(unsigned*)(outL + idx) = l2;
            }
        }
    }
}

// ---------------- flash attention, tensor-core, bf16-split ----------------
// BQ=128 (warp m16), BK=64, Dk=64. Double-buffered K/V/mask via cp.async.
#define AK_H 0
#define AK_L 9216
#define AV_H 18432
#define AV_L 27648
#define A_MS 36864
#define A_BUF 37120

__global__ __launch_bounds__(256)
void flash_mma(const bf16* __restrict__ qh, const bf16* __restrict__ ql,
               const bf16* __restrict__ kh, const bf16* __restrict__ kl,
               const bf16* __restrict__ vh, const bf16* __restrict__ vl,
               bf16* __restrict__ aoh, bf16* __restrict__ aol)
{
    extern __shared__ char smem[];
    const unsigned sb = (unsigned)__cvta_generic_to_shared(smem);
    const int tid = threadIdx.x, lane = tid & 31, w = tid >> 5;
    const int bh = blockIdx.y;
    const int b_ = bh / NHEADS, h_ = bh % NHEADS;
    const int q0 = blockIdx.x * 128;

    // ---- stage Q, build register fragments ----
    unsigned qfh[4][4], qfl[4][4];
    {
        int r = tid >> 2, cb = (tid & 3) * 2;
#pragma unroll
        for (int p = 0; p < 2; p++) {
            const bf16* gq_h = qh + ((size_t)bh * SEQ + q0 + p * 64 + r) * DKH + cb * 8;
            const bf16* gq_l = ql + ((size_t)bh * SEQ + q0 + p * 64 + r) * DKH + cb * 8;
            uint4 h0 = *(const uint4*)gq_h;
            uint4 h1 = *(const uint4*)(gq_h + 8);
            uint4 l0 = *(const uint4*)gq_l;
            uint4 l1 = *(const uint4*)(gq_l + 8);
            __syncthreads();
            *(uint4*)(smem + AK_H + r * 144 + cb * 16)      = h0;
            *(uint4*)(smem + AK_H + r * 144 + cb * 16 + 16) = h1;
            *(uint4*)(smem + AK_L + r * 144 + cb * 16)      = l0;
            *(uint4*)(smem + AK_L + r * 144 + cb * 16 + 16) = l1;
            __syncthreads();
            if ((w >> 2) == p) {
                int lrow = (w - p * 4) * 16 + (lane & 15);
#pragma unroll
                for (int ks = 0; ks < 4; ks++) {
                    unsigned addr = sb + AK_H + lrow * 144 + (ks * 2 + (lane >> 4)) * 16;
                    ldsm4(qfh[ks], addr);
                    ldsm4(qfl[ks], addr + (AK_L - AK_H));
                }
            }
        }
        __syncthreads();
    }

    // ---- K/V/mask pipeline ----
    const int r = tid >> 2, cb = (tid & 3) * 2;
    const bf16* gK_h = kh + ((size_t)bh * SEQ + r) * DKH + cb * 8;
    const bf16* gK_l = kl + ((size_t)bh * SEQ + r) * DKH + cb * 8;
    const bf16* gV_h = vh + ((size_t)bh * SEQ + r) * DKH + cb * 8;
    const bf16* gV_l = vl + ((size_t)bh * SEQ + r) * DKH + cb * 8;
    const float* gM = g_maskf + b_ * SEQ;
    const unsigned st = r * 144 + cb * 16;

    auto issue = [&](int kt, int buf) {
        unsigned base = sb + buf * A_BUF;
        size_t ke = (size_t)kt * 64 * DKH;
#pragma unroll
        for (int c = 0; c < 2; c++) {
            cp16(base + AK_H + st + c * 16, gK_h + ke + c * 8);
            cp16(base + AK_L + st + c * 16, gK_l + ke + c * 8);
            cp16(base + AV_H + st + c * 16, gV_h + ke + c * 8);
            cp16(base + AV_L + st + c * 16, gV_l + ke + c * 8);
        }
        if (tid < 16) cp16(base + A_MS + tid * 16, gM + kt * 64 + tid * 4);
        cp_commit();
    };

    float o[8][4] = {};
    float mi[2] = {-1e30f, -1e30f};
    float li[2] = {0.f, 0.f};

    issue(0, 0);
    const int NT = SEQ / 64;
    for (int kt = 0; kt < NT; kt++) {
        int buf = kt & 1;
        unsigned base = sb + buf * A_BUF;
        if (kt + 1 < NT) { issue(kt + 1, buf ^ 1); cp_wait1(); }
        else             { cp_wait0(); }
        __syncthreads();

        // S = Q K^T
        float s[8][4] = {};
        const unsigned ar = lane & 15;
#pragma unroll
        for (int ks = 0; ks < 4; ks++) {
            const unsigned ac = ks * 2 + (lane >> 4);
#pragma unroll
            for (int ni2 = 0; ni2 < 4; ni2++) {
                unsigned bhr[4], blr[4];
                unsigned addr = base + AK_H + (ni2 * 16 + ar) * 144 + ac * 16;
                ldsm4(bhr, addr);
                ldsm4(blr, addr + (AK_L - AK_H));
                mma16816(s[ni2 * 2],     qfh[ks], bhr[0], bhr[2]);
                mma16816(s[ni2 * 2 + 1], qfh[ks], bhr[1], bhr[3]);
                mma16816(s[ni2 * 2],     qfh[ks], blr[0], blr[2]);
                mma16816(s[ni2 * 2 + 1], qfh[ks], blr[1], blr[3]);
                mma16816(s[ni2 * 2],     qfl[ks], bhr[0], bhr[2]);
                mma16816(s[ni2 * 2 + 1], qfl[ks], bhr[1], bhr[3]);
            }
        }

        // mask selectors for this tile (16 cols per thread)
        const float* msk = (const float*)(smem + buf * A_BUF + A_MS);
        float msel[16];
#pragma unroll
        for (int ni = 0; ni < 8; ni++) {
            int col = ni * 8 + (lane & 3) * 2;
            msel[ni * 2]     = msk[col];
            msel[ni * 2 + 1] = msk[col + 1];
        }

        // online softmax (2 rows per thread)
#pragma unroll
        for (int rr = 0; rr < 2; rr++) {
            float xv[16];
            float rmax = -1e30f;
#pragma unroll
            for (int ni = 0; ni < 8; ni++)
#pragma unroll
                for (int jj = 0; jj < 2; jj++) {
                    float x = (msel[ni * 2 + jj] != 0.f) ? -1e9f
                              : s[ni][rr * 2 + jj] * 0.125f;
                    xv[ni * 2 + jj] = x;
                    rmax = fmaxf(rmax, x);
                }
            rmax = fmaxf(rmax, __shfl_xor_sync(0xffffffffu, rmax, 1));
            rmax = fmaxf(rmax, __shfl_xor_sync(0xffffffffu, rmax, 2));
            float mnew = fmaxf(mi[rr], rmax);
            float fac = __expf(mi[rr] - mnew);
            float rsum = 0.f;
#pragma unroll
            for (int ix = 0; ix < 16; ix++) {
                float p = __expf(xv[ix] - mnew);
                s[ix >> 1][rr * 2 + (ix & 1)] = p;
                rsum += p;
            }
            rsum += __shfl_xor_sync(0xffffffffu, rsum, 1);
            rsum += __shfl_xor_sync(0xffffffffu, rsum, 2);
            li[rr] = li[rr] * fac + rsum;
            mi[rr] = mnew;
#pragma unroll
            for (int dj = 0; dj < 8; dj++) {
                o[dj][rr * 2]     *= fac;
                o[dj][rr * 2 + 1] *= fac;
            }
        }

        // O += P V
#pragma unroll
        for (int kk = 0; kk < 4; kk++) {
            unsigned ph[4], pl[4];
            split2(s[2 * kk][0], s[2 * kk][1], ph[0], pl[0]);
            split2(s[2 * kk][2], s[2 * kk][3], ph[1], pl[1]);
            split2(s[2 * kk + 1][0], s[2 * kk + 1][1], ph[2], pl[2]);
            split2(s[2 * kk + 1][2], s[2 * kk + 1][3], ph[3], pl[3]);
            // trans-ldmatrix addressing for V [k][d]
            int g = lane >> 3;
            int vrow = kk * 16 + (g & 1) * 8 + (lane & 7);
#pragma unroll
            for (int dj2 = 0; dj2 < 4; dj2++) {
                int dcol = dj2 * 16 + (g >> 1) * 8;
                unsigned addr = base + AV_H + vrow * 144 + dcol * 2;
                unsigned vhr[4], vlr[4];
                ldsm4t(vhr, addr);
                ldsm4t(vlr, addr + (AV_L - AV_H));
                mma16816(o[dj2 * 2],     ph, vhr[0], vhr[1]);
                mma16816(o[dj2 * 2 + 1], ph, vhr[2], vhr[3]);
                mma16816(o[dj2 * 2],     ph, vlr[0], vlr[1]);
                mma16816(o[dj2 * 2 + 1], ph, vlr[2], vlr[3]);
                mma16816(o[dj2 * 2],     pl, vhr[0], vhr[1]);
                mma16816(o[dj2 * 2 + 1], pl, vhr[2], vhr[3]);
            }
        }
        __syncthreads();
    }

    // epilogue: write bf16 hi/lo attn output at [b, s, h*64+d]
#pragma unroll
    for (int rr = 0; rr < 2; rr++) {
        int qrow = q0 + w * 16 + (lane >> 2) + rr * 8;
        float inv = 1.f / li[rr];
        size_t rowoff = ((size_t)(b_ * SEQ + qrow)) * D_MODEL + h_ * DKH;
#pragma unroll
        for (int dj = 0; dj < 8; dj++) {
            int d = dj * 8 + (lane & 3) * 2;
            float v0 = o[dj][rr * 2]     * inv;
            float v1 = o[dj][rr * 2 + 1] * inv;
            unsigned h2, l2;
            split2(v0, v1, h2, l2);
            *(unsigned*)(aoh + rowoff + d) = h2;
            *(unsigned*)(aol + rowoff + d) = l2;
        }
    }
}

// ---------------- LayerNorm (torch semantics: ddof=1, /(std+eps)) ----------------
__global__ __launch_bounds__(256)
void layernorm_kernel(const float* __restrict__ in, const float* __restrict__ gamma,
                      const float* __restrict__ beta, float* __restrict__ out,
                      bf16* __restrict__ outH, bf16* __restrict__ outL)
{
    __shared__ float red[32];
    __shared__ float bc[2];
    const int row = blockIdx.x;
    const int tid = threadIdx.x;
    const int lane = tid & 31, wid = tid >> 5;

    float v[3];
    float s1 = 0.f;
#pragma unroll
    for (int t = 0; t < 3; t++) {
        v[t] = in[(size_t)row * D_MODEL + tid + t * 256];
        s1 += v[t];
    }
#pragma unroll
    for (int off = 16; off >= 1; off >>= 1) s1 += __shfl_xor_sync(0xffffffffu, s1, off);
    if (lane == 0) red[wid] = s1;
    __syncthreads();
    if (tid == 0) {
        float acc = 0.f;
        for (int w = 0; w < 8; w++) acc += red[w];
        bc[0] = acc / (float)D_MODEL;
    }
    __syncthreads();
    float mean = bc[0];

    float s2 = 0.f;
#pragma unroll
    for (int t = 0; t < 3; t++) {
        float d = v[t] - mean;
        s2 += d * d;
    }
#pragma unroll
    for (int off = 16; off >= 1; off >>= 1) s2 += __shfl_xor_sync(0xffffffffu, s2, off);
    if (lane == 0) red[wid] = s2;
    __syncthreads();
    if (tid == 0) {
        float acc = 0.f;
        for (int w = 0; w < 8; w++) acc += red[w];
        float var = acc / (float)(D_MODEL - 1);
        bc[1] = 1.f / (sqrtf(var) + LN_EPS);
    }
    __syncthreads();
    float inv = bc[1];

#pragma unroll
    for (int t = 0; t < 3; t++) {
        int c = tid + t * 256;
        float y = gamma[c] * (v[t] - mean) * inv + beta[c];
        out[(size_t)row * D_MODEL + c] = y;
        if (outH) {
            bf16 h = __float2bfloat16(y);
            outH[(size_t)row * D_MODEL + c] = h;
            outL[(size_t)row * D_MODEL + c] = __float2bfloat16(y - __bfloat162float(h));
        }
    }
}

// ---------------- launch ----------------
extern "C" void kernel_launch(void* const* d_in, const int* in_sizes, int n_in,
                              void* d_out, int out_size)
{
    const float* x   = (const float*)d_in[0];
    const void*  mraw = (const void*)d_in[1];
    const float* wq = (const float*)d_in[2];
    const float* bq = (const float*)d_in[3];
    const float* wk = (const float*)d_in[4];
    const float* bk = (const float*)d_in[5];
    const float* wv = (const float*)d_in[6];
    const float* bv = (const float*)d_in[7];
    const float* wo = (const float*)d_in[8];
    const float* bo = (const float*)d_in[9];
    const float* w1 = (const float*)d_in[10];
    const float* b1 = (const float*)d_in[11];
    const float* w2 = (const float*)d_in[12];
    const float* b2 = (const float*)d_in[13];
    const float* g1 = (const float*)d_in[14];
    const float* be1 = (const float*)d_in[15];
    const float* g2 = (const float*)d_in[16];
    const float* be2 = (const float*)d_in[17];
    float* outp = (float*)d_out;

    bf16 *xh, *xl, *wqh, *wql, *wkh, *wkl, *wvh, *wvl, *woh, *wol;
    bf16 *w1h, *w1l, *w2h, *w2l, *qh, *ql, *kh, *kl, *vh, *vl;
    bf16 *ah, *al, *ffh, *ffl, *x1h, *x1l;
    float *res1, *x1, *res2;
    cudaGetSymbolAddress((void**)&xh,  g_xh);  cudaGetSymbolAddress((void**)&xl,  g_xl);
    cudaGetSymbolAddress((void**)&wqh, g_wqh); cudaGetSymbolAddress((void**)&wql, g_wql);
    cudaGetSymbolAddress((void**)&wkh, g_wkh); cudaGetSymbolAddress((void**)&wkl, g_wkl);
    cudaGetSymbolAddress((void**)&wvh, g_wvh); cudaGetSymbolAddress((void**)&wvl, g_wvl);
    cudaGetSymbolAddress((void**)&woh, g_woh); cudaGetSymbolAddress((void**)&wol, g_wol);
    cudaGetSymbolAddress((void**)&w1h, g_w1h); cudaGetSymbolAddress((void**)&w1l, g_w1l);
    cudaGetSymbolAddress((void**)&w2h, g_w2h); cudaGetSymbolAddress((void**)&w2l, g_w2l);
    cudaGetSymbolAddress((void**)&qh,  g_qh);  cudaGetSymbolAddress((void**)&ql,  g_ql);
    cudaGetSymbolAddress((void**)&kh,  g_kh);  cudaGetSymbolAddress((void**)&kl,  g_kl);
    cudaGetSymbolAddress((void**)&vh,  g_vh);  cudaGetSymbolAddress((void**)&vl,  g_vl);
    cudaGetSymbolAddress((void**)&ah,  g_ah);  cudaGetSymbolAddress((void**)&al,  g_al);
    cudaGetSymbolAddress((void**)&ffh, g_ffh); cudaGetSymbolAddress((void**)&ffl, g_ffl);
    cudaGetSymbolAddress((void**)&x1h, g_x1h); cudaGetSymbolAddress((void**)&x1l, g_x1l);
    cudaGetSymbolAddress((void**)&res1, g_res1);
    cudaGetSymbolAddress((void**)&x1,   g_x1);
    cudaGetSymbolAddress((void**)&res2, g_res2);

    const int GSM = 2 * GSM_BUF;     // 81920
    const int ASM = 2 * A_BUF;       // 74240
    cudaFuncSetAttribute(gemm_mma<EPI_QKV>,  cudaFuncAttributeMaxDynamicSharedMemorySize, GSM);
    cudaFuncSetAttribute(gemm_mma<EPI_ORES>, cudaFuncAttributeMaxDynamicSharedMemorySize, GSM);
    cudaFuncSetAttribute(gemm_mma<EPI_FF1>,  cudaFuncAttributeMaxDynamicSharedMemorySize, GSM);
    cudaFuncSetAttribute(gemm_mma<EPI_FF2>,  cudaFuncAttributeMaxDynamicSharedMemorySize, GSM);
    cudaFuncSetAttribute(flash_mma, cudaFuncAttributeMaxDynamicSharedMemorySize, ASM);

    dim3 blk(256);

    // mask + input/weight conversions
    mask_canon_kernel<<<1, 256>>>(mraw);
    cvt_split<<<(MROWS * D_MODEL) / 1024, blk>>>(x, xh, xl, MROWS * D_MODEL);
    cvt_split<<<(D_MODEL * D_MODEL) / 1024, blk>>>(wq, wqh, wql, D_MODEL * D_MODEL);
    cvt_split<<<(D_MODEL * D_MODEL) / 1024, blk>>>(wk, wkh, wkl, D_MODEL * D_MODEL);
    cvt_split<<<(D_MODEL * D_MODEL) / 1024, blk>>>(wv, wvh, wvl, D_MODEL * D_MODEL);
    cvt_split<<<(D_MODEL * D_MODEL) / 1024, blk>>>(wo, woh, wol, D_MODEL * D_MODEL);
    cvt_split<<<(DFF * D_MODEL) / 1024, blk>>>(w1, w1h, w1l, DFF * D_MODEL);
    cvt_split<<<(D_MODEL * DFF) / 1024, blk>>>(w2, w2h, w2l, D_MODEL * DFF);

    dim3 gP(MROWS / 128, D_MODEL / 128);   // (32, 6)
    dim3 gF1(MROWS / 128, DFF / 128);      // (32, 24)

    // QKV projections → bf16 hi/lo [b,h,s,d]
    gemm_mma<EPI_QKV><<<gP, blk, GSM>>>(xh, xl, wqh, wql, bq, nullptr, nullptr, qh, ql, D_MODEL, D_MODEL);
    gemm_mma<EPI_QKV><<<gP, blk, GSM>>>(xh, xl, wkh, wkl, bk, nullptr, nullptr, kh, kl, D_MODEL, D_MODEL);
    gemm_mma<EPI_QKV><<<gP, blk, GSM>>>(xh, xl, wvh, wvl, bv, nullptr, nullptr, vh, vl, D_MODEL, D_MODEL);

    // attention → bf16 hi/lo [m, 768]
    flash_mma<<<dim3(SEQ / 128, BHTOT), blk, ASM>>>(qh, ql, kh, kl, vh, vl, ah, al);

    // O projection + residual(x) → res1; LN1 → x1 (fp32 + bf16)
    gemm_mma<EPI_ORES><<<gP, blk, GSM>>>(ah, al, woh, wol, bo, x, res1, nullptr, nullptr, D_MODEL, D_MODEL);
    layernorm_kernel<<<MROWS, blk>>>(res1, g1, be1, x1, x1h, x1l);

    // FFN
    gemm_mma<EPI_FF1><<<gF1, blk, GSM>>>(x1h, x1l, w1h, w1l, b1, nullptr, nullptr, ffh, ffl, D_MODEL, DFF);
    gemm_mma<EPI_FF2><<<gP, blk, GSM>>>(ffh, ffl, w2h, w2l, b2, x1, res2, nullptr, nullptr, DFF, D_MODEL);
    layernorm_kernel<<<MROWS, blk>>>(res2, g2, be2, outp, nullptr, nullptr);
}

// round 7
// speedup vs baseline: 5.4558x; 1.4198x over previous
#include <cuda_runtime.h>
#include <cuda_bf16.h>

#define D_MODEL 768
#define NHEADS  12
#define DKH     64
#define SEQ     2048
#define BATCH   2
#define DFF     3072
#define MROWS   (BATCH*SEQ)          // 4096
#define BHTOT   (BATCH*NHEADS)       // 24
#define LN_EPS  1e-6f

typedef __nv_bfloat16 bf16;
typedef __nv_bfloat162 bf162;

// ---------------- scratch (static device memory, allowed) ----------------
__device__ __align__(16) bf16 g_xh [MROWS*D_MODEL];
__device__ __align__(16) bf16 g_wqh[D_MODEL*D_MODEL];
__device__ __align__(16) bf16 g_wkh[D_MODEL*D_MODEL];
__device__ __align__(16) bf16 g_wvh[D_MODEL*D_MODEL];
__device__ __align__(16) bf16 g_woh[D_MODEL*D_MODEL];
__device__ __align__(16) bf16 g_w1h[DFF*D_MODEL];
__device__ __align__(16) bf16 g_w1l[DFF*D_MODEL];
__device__ __align__(16) bf16 g_w2h[D_MODEL*DFF];
__device__ __align__(16) bf16 g_w2l[D_MODEL*DFF];
__device__ __align__(16) bf16 g_qh [BHTOT*SEQ*DKH];
__device__ __align__(16) bf16 g_kh [BHTOT*SEQ*DKH];
__device__ __align__(16) bf16 g_vh [BHTOT*SEQ*DKH];
__device__ __align__(16) bf16 g_ah [MROWS*D_MODEL];
__device__ __align__(16) bf16 g_ffh[MROWS*DFF];
__device__ __align__(16) bf16 g_ffl[MROWS*DFF];
__device__ __align__(16) bf16 g_x1h[MROWS*D_MODEL];
__device__ __align__(16) bf16 g_x1l[MROWS*D_MODEL];
__device__ __align__(16) float g_res1[MROWS*D_MODEL];
__device__ __align__(16) float g_x1 [MROWS*D_MODEL];
__device__ __align__(16) float g_res2[MROWS*D_MODEL];
__device__ __align__(16) float g_maskf[BATCH*SEQ];   // 1.0 = masked, 0.0 = keep

// ---------------- asm helpers ----------------
__device__ __forceinline__ void ldsm4(unsigned* r, unsigned addr) {
    asm volatile("ldmatrix.sync.aligned.m8n8.x4.shared.b16 {%0,%1,%2,%3}, [%4];"
        : "=r"(r[0]), "=r"(r[1]), "=r"(r[2]), "=r"(r[3]) : "r"(addr));
}
__device__ __forceinline__ void ldsm4t(unsigned* r, unsigned addr) {
    asm volatile("ldmatrix.sync.aligned.m8n8.x4.trans.shared.b16 {%0,%1,%2,%3}, [%4];"
        : "=r"(r[0]), "=r"(r[1]), "=r"(r[2]), "=r"(r[3]) : "r"(addr));
}
__device__ __forceinline__ void mma16816(float* c, const unsigned* a, unsigned b0, unsigned b1) {
    asm volatile("mma.sync.aligned.m16n8k16.row.col.f32.bf16.bf16.f32 "
        "{%0,%1,%2,%3}, {%4,%5,%6,%7}, {%8,%9}, {%0,%1,%2,%3};"
        : "+f"(c[0]), "+f"(c[1]), "+f"(c[2]), "+f"(c[3])
        : "r"(a[0]), "r"(a[1]), "r"(a[2]), "r"(a[3]), "r"(b0), "r"(b1));
}
__device__ __forceinline__ void cp16(unsigned saddr, const void* gptr) {
    asm volatile("cp.async.ca.shared.global [%0], [%1], 16;" :: "r"(saddr), "l"(gptr));
}
__device__ __forceinline__ void cp_commit() { asm volatile("cp.async.commit_group;"); }
__device__ __forceinline__ void cp_wait1() { asm volatile("cp.async.wait_group 1;"); }
__device__ __forceinline__ void cp_wait0() { asm volatile("cp.async.wait_group 0;"); }

__device__ __forceinline__ unsigned pkbf(float a, float b) {
    bf162 t = __floats2bfloat162_rn(a, b);
    return reinterpret_cast<unsigned&>(t);
}
// split a pair of fp32 into packed bf16 hi and lo parts
__device__ __forceinline__ void split2(float e0, float e1, unsigned& h2, unsigned& l2) {
    bf162 h = __floats2bfloat162_rn(e0, e1);
    h2 = reinterpret_cast<unsigned&>(h);
    float f0 = __bfloat162float(h.x);
    float f1 = __bfloat162float(h.y);
    bf162 l = __floats2bfloat162_rn(e0 - f0, e1 - f1);
    l2 = reinterpret_cast<unsigned&>(l);
}

// ---------------- mask canonicalization → float selector ----------------
__global__ void mask_canon_kernel(const void* __restrict__ mraw)
{
    __shared__ int s_flag;
    const unsigned int* w = (const unsigned int*)mraw;
    if (threadIdx.x == 0) s_flag = 0;
    __syncthreads();
    int any = 0;
    for (int i = threadIdx.x; i < 1024; i += 256)
        if (w[i] > 1u) any = 1;
    if (any) atomicOr(&s_flag, 1);
    __syncthreads();
    if (s_flag) {
        const unsigned char* mb = (const unsigned char*)mraw;
        for (int i = threadIdx.x; i < BATCH * SEQ; i += 256)
            g_maskf[i] = mb[i] ? 1.0f : 0.0f;
    } else {
        const int* mi = (const int*)mraw;
        for (int i = threadIdx.x; i < BATCH * SEQ; i += 256)
            g_maskf[i] = mi[i] ? 1.0f : 0.0f;
    }
}

// ---------------- fp32 -> bf16 converts ----------------
__global__ void cvt_split(const float* __restrict__ s, bf16* __restrict__ h,
                          bf16* __restrict__ l, int n)
{
    int i = (blockIdx.x * 256 + threadIdx.x) * 4;
    if (i >= n) return;
    float4 v = *(const float4*)(s + i);
    unsigned h01, l01, h23, l23;
    split2(v.x, v.y, h01, l01);
    split2(v.z, v.w, h23, l23);
    *(unsigned*)(h + i)     = h01;
    *(unsigned*)(h + i + 2) = h23;
    *(unsigned*)(l + i)     = l01;
    *(unsigned*)(l + i + 2) = l23;
}
__global__ void cvt1(const float* __restrict__ s, bf16* __restrict__ h, int n)
{
    int i = (blockIdx.x * 256 + threadIdx.x) * 4;
    if (i >= n) return;
    float4 v = *(const float4*)(s + i);
    *(unsigned*)(h + i)     = pkbf(v.x, v.y);
    *(unsigned*)(h + i + 2) = pkbf(v.z, v.w);
}

// ---------------- tensor-core GEMM: C[m,n] = sum_k A[m,k]*W[n,k] ----------------
// block 128x128, ktile 32, 8 warps (warp tile 32m x 64n).
// SPLIT=3: bf16-split 3-mma (hi*hi + hi*lo + lo*hi). SPLIT=1: plain bf16.
enum { EPI_QKV = 0, EPI_ORES = 1, EPI_FF1 = 2, EPI_FF2 = 3 };

template<int EPI, int SPLIT>
__global__ __launch_bounds__(256, 2)
void gemm_mma(const bf16* __restrict__ Ah, const bf16* __restrict__ Al,
              const bf16* __restrict__ Wh, const bf16* __restrict__ Wl,
              const float* __restrict__ bias, const float* __restrict__ res,
              float* __restrict__ outF, bf16* __restrict__ outH, bf16* __restrict__ outL,
              int Kdim, int Ndim)
{
    const int WOFF  = (SPLIT == 3) ? 20480 : 10240;  // W region offset
    const int BUFSZ = (SPLIT == 3) ? 40960 : 20480;

    extern __shared__ char smem[];
    const unsigned sb = (unsigned)__cvta_generic_to_shared(smem);
    const int tid = threadIdx.x, lane = tid & 31, warp = tid >> 5;
    const int wm = warp & 3, wn = warp >> 2;
    const int m0 = blockIdx.x * 128, n0 = blockIdx.y * 128;

    const int lr = tid >> 1;          // 0..127
    const int lc = (tid & 1) * 2;     // chunk base 0 or 2
    const bf16* gAh = Ah + (size_t)(m0 + lr) * Kdim + lc * 8;
    const bf16* gWh = Wh + (size_t)(n0 + lr) * Kdim + lc * 8;
    const bf16* gAl = (SPLIT == 3) ? Al + (size_t)(m0 + lr) * Kdim + lc * 8 : nullptr;
    const bf16* gWl = (SPLIT == 3) ? Wl + (size_t)(n0 + lr) * Kdim + lc * 8 : nullptr;
    const unsigned st = lr * 80 + lc * 16;

    float acc[2][8][4] = {};
    const int nk = Kdim / 32;

    auto issue = [&](int kt, int buf) {
        unsigned b = sb + buf * BUFSZ;
        int ke = kt * 32;
#pragma unroll
        for (int c = 0; c < 2; c++) {
            cp16(b +        st + c * 16, gAh + ke + c * 8);
            cp16(b + WOFF + st + c * 16, gWh + ke + c * 8);
            if (SPLIT == 3) {
                cp16(b + 10240 +        st + c * 16, gAl + ke + c * 8);
                cp16(b + WOFF + 10240 + st + c * 16, gWl + ke + c * 8);
            }
        }
        cp_commit();
    };

    issue(0, 0);
    for (int kt = 0; kt < nk; kt++) {
        int buf = kt & 1;
        if (kt + 1 < nk) { issue(kt + 1, buf ^ 1); cp_wait1(); }
        else             { cp_wait0(); }
        __syncthreads();

        unsigned b = sb + buf * BUFSZ;
        const unsigned ar = lane & 15;
#pragma unroll
        for (int ks = 0; ks < 2; ks++) {
            const unsigned ac = ks * 2 + (lane >> 4);
            unsigned ah[2][4], al[2][4];
#pragma unroll
            for (int mi = 0; mi < 2; mi++) {
                unsigned addr = b + (wm * 32 + mi * 16 + ar) * 80 + ac * 16;
                ldsm4(ah[mi], addr);
                if (SPLIT == 3) ldsm4(al[mi], addr + 10240);
            }
#pragma unroll
            for (int ni2 = 0; ni2 < 4; ni2++) {
                unsigned bh[4], bl[4];
                unsigned addr = b + WOFF + (wn * 64 + ni2 * 16 + ar) * 80 + ac * 16;
                ldsm4(bh, addr);
                if (SPLIT == 3) ldsm4(bl, addr + 10240);
#pragma unroll
                for (int mi = 0; mi < 2; mi++) {
                    mma16816(acc[mi][ni2 * 2],     ah[mi], bh[0], bh[2]);
                    mma16816(acc[mi][ni2 * 2 + 1], ah[mi], bh[1], bh[3]);
                    if (SPLIT == 3) {
                        mma16816(acc[mi][ni2 * 2],     ah[mi], bl[0], bl[2]);
                        mma16816(acc[mi][ni2 * 2 + 1], ah[mi], bl[1], bl[3]);
                        mma16816(acc[mi][ni2 * 2],     al[mi], bh[0], bh[2]);
                        mma16816(acc[mi][ni2 * 2 + 1], al[mi], bh[1], bh[3]);
                    }
                }
            }
        }
        __syncthreads();
    }

    // epilogue
#pragma unroll
    for (int mi = 0; mi < 2; mi++)
#pragma unroll
    for (int rr = 0; rr < 2; rr++) {
        int m = m0 + wm * 32 + mi * 16 + (lane >> 2) + rr * 8;
#pragma unroll
        for (int ni = 0; ni < 8; ni++) {
            int n = n0 + wn * 64 + ni * 8 + (lane & 3) * 2;
            float v0 = acc[mi][ni][rr * 2 + 0] + bias[n];
            float v1 = acc[mi][ni][rr * 2 + 1] + bias[n + 1];
            if (EPI == EPI_QKV) {
                int b_ = m >> 11, s_ = m & (SEQ - 1);
                int h_ = n >> 6, d_ = n & 63;
                size_t idx = ((size_t)(b_ * NHEADS + h_) * SEQ + s_) * DKH + d_;
                *(unsigned*)(outH + idx) = pkbf(v0, v1);
            } else if (EPI == EPI_ORES || EPI == EPI_FF2) {
                v0 += res[(size_t)m * Ndim + n];
                v1 += res[(size_t)m * Ndim + n + 1];
                outF[(size_t)m * Ndim + n]     = v0;
                outF[(size_t)m * Ndim + n + 1] = v1;
            } else { // EPI_FF1: relu + bf16 split
                v0 = fmaxf(v0, 0.f);
                v1 = fmaxf(v1, 0.f);
                unsigned h2, l2;
                split2(v0, v1, h2, l2);
                size_t idx = (size_t)m * Ndim + n;
                *(unsigned*)(outH + idx) = h2;
                *(unsigned*)(outL + idx) = l2;
            }
        }
    }
}

// ---------------- flash attention, tensor-core, single-pass bf16 ----------------
// BQ=128 (warp m16), BK=64, Dk=64. Double-buffered K/V/mask via cp.async.
#define FK 0
#define FV 9216
#define FM 18432
#define F_BUF 18688

__global__ __launch_bounds__(256)
void flash_mma(const bf16* __restrict__ qm, const bf16* __restrict__ km,
               const bf16* __restrict__ vm, bf16* __restrict__ ao)
{
    extern __shared__ char smem[];
    const unsigned sb = (unsigned)__cvta_generic_to_shared(smem);
    const int tid = threadIdx.x, lane = tid & 31, w = tid >> 5;
    const int bh = blockIdx.y;
    const int b_ = bh / NHEADS, h_ = bh % NHEADS;
    const int q0 = blockIdx.x * 128;

    // ---- stage Q (two 64-row passes through FK region), build register frags ----
    unsigned qf[4][4];
    {
        int r = tid >> 2, cbq = (tid & 3) * 2;
#pragma unroll
        for (int p = 0; p < 2; p++) {
            const bf16* gq = qm + ((size_t)bh * SEQ + q0 + p * 64 + r) * DKH + cbq * 8;
            uint4 h0 = *(const uint4*)gq;
            uint4 h1 = *(const uint4*)(gq + 8);
            __syncthreads();
            *(uint4*)(smem + FK + r * 144 + cbq * 16)      = h0;
            *(uint4*)(smem + FK + r * 144 + cbq * 16 + 16) = h1;
            __syncthreads();
            if ((w >> 2) == p) {
                int lrow = (w - p * 4) * 16 + (lane & 15);
#pragma unroll
                for (int ks = 0; ks < 4; ks++) {
                    unsigned addr = sb + FK + lrow * 144 + (ks * 2 + (lane >> 4)) * 16;
                    ldsm4(qf[ks], addr);
                }
            }
        }
        __syncthreads();
    }

    // ---- K/V/mask pipeline ----
    const int r = tid >> 2, cb = (tid & 3) * 2;
    const bf16* gK = km + ((size_t)bh * SEQ + r) * DKH + cb * 8;
    const bf16* gV = vm + ((size_t)bh * SEQ + r) * DKH + cb * 8;
    const float* gM = g_maskf + b_ * SEQ;
    const unsigned st = r * 144 + cb * 16;

    auto issue = [&](int kt, int buf) {
        unsigned base = sb + buf * F_BUF;
        size_t ke = (size_t)kt * 64 * DKH;
#pragma unroll
        for (int c = 0; c < 2; c++) {
            cp16(base + FK + st + c * 16, gK + ke + c * 8);
            cp16(base + FV + st + c * 16, gV + ke + c * 8);
        }
        if (tid < 16) cp16(base + FM + tid * 16, gM + kt * 64 + tid * 4);
        cp_commit();
    };

    float o[8][4] = {};
    float mi[2] = {-1e30f, -1e30f};
    float li[2] = {0.f, 0.f};

    issue(0, 0);
    const int NT = SEQ / 64;
    for (int kt = 0; kt < NT; kt++) {
        int buf = kt & 1;
        unsigned base = sb + buf * F_BUF;
        if (kt + 1 < NT) { issue(kt + 1, buf ^ 1); cp_wait1(); }
        else             { cp_wait0(); }
        __syncthreads();

        // S = Q K^T
        float s[8][4] = {};
        const unsigned ar = lane & 15;
#pragma unroll
        for (int ks = 0; ks < 4; ks++) {
            const unsigned ac = ks * 2 + (lane >> 4);
#pragma unroll
            for (int ni2 = 0; ni2 < 4; ni2++) {
                unsigned kr[4];
                ldsm4(kr, base + FK + (ni2 * 16 + ar) * 144 + ac * 16);
                mma16816(s[ni2 * 2],     qf[ks], kr[0], kr[2]);
                mma16816(s[ni2 * 2 + 1], qf[ks], kr[1], kr[3]);
            }
        }

        // mask selectors for this tile (16 cols per thread)
        const float* msk = (const float*)(smem + buf * F_BUF + FM);
        float msel[16];
#pragma unroll
        for (int ni = 0; ni < 8; ni++) {
            int col = ni * 8 + (lane & 3) * 2;
            msel[ni * 2]     = msk[col];
            msel[ni * 2 + 1] = msk[col + 1];
        }

        // online softmax (2 rows per thread)
#pragma unroll
        for (int rr = 0; rr < 2; rr++) {
            float xv[16];
            float rmax = -1e30f;
#pragma unroll
            for (int ni = 0; ni < 8; ni++)
#pragma unroll
                for (int jj = 0; jj < 2; jj++) {
                    float x = (msel[ni * 2 + jj] != 0.f) ? -1e9f
                              : s[ni][rr * 2 + jj] * 0.125f;
                    xv[ni * 2 + jj] = x;
                    rmax = fmaxf(rmax, x);
                }
            rmax = fmaxf(rmax, __shfl_xor_sync(0xffffffffu, rmax, 1));
            rmax = fmaxf(rmax, __shfl_xor_sync(0xffffffffu, rmax, 2));
            float mnew = fmaxf(mi[rr], rmax);
            float fac = __expf(mi[rr] - mnew);
            float rsum = 0.f;
#pragma unroll
            for (int ix = 0; ix < 16; ix++) {
                float p = __expf(xv[ix] - mnew);
                s[ix >> 1][rr * 2 + (ix & 1)] = p;
                rsum += p;
            }
            rsum += __shfl_xor_sync(0xffffffffu, rsum, 1);
            rsum += __shfl_xor_sync(0xffffffffu, rsum, 2);
            li[rr] = li[rr] * fac + rsum;
            mi[rr] = mnew;
#pragma unroll
            for (int dj = 0; dj < 8; dj++) {
                o[dj][rr * 2]     *= fac;
                o[dj][rr * 2 + 1] *= fac;
            }
        }

        // O += P V
#pragma unroll
        for (int kk = 0; kk < 4; kk++) {
            unsigned ph[4];
            ph[0] = pkbf(s[2 * kk][0], s[2 * kk][1]);
            ph[1] = pkbf(s[2 * kk][2], s[2 * kk][3]);
            ph[2] = pkbf(s[2 * kk + 1][0], s[2 * kk + 1][1]);
            ph[3] = pkbf(s[2 * kk + 1][2], s[2 * kk + 1][3]);
            // trans-ldmatrix addressing for V [k][d]
            int g = lane >> 3;
            int vrow = kk * 16 + (g & 1) * 8 + (lane & 7);
#pragma unroll
            for (int dj2 = 0; dj2 < 4; dj2++) {
                int dcol = dj2 * 16 + (g >> 1) * 8;
                unsigned vr[4];
                ldsm4t(vr, base + FV + vrow * 144 + dcol * 2);
                mma16816(o[dj2 * 2],     ph, vr[0], vr[1]);
                mma16816(o[dj2 * 2 + 1], ph, vr[2], vr[3]);
            }
        }
        __syncthreads();
    }

    // epilogue: write bf16 attn output at [b, s, h*64+d]
#pragma unroll
    for (int rr = 0; rr < 2; rr++) {
        int qrow = q0 + w * 16 + (lane >> 2) + rr * 8;
        float inv = 1.f / li[rr];
        size_t rowoff = ((size_t)(b_ * SEQ + qrow)) * D_MODEL + h_ * DKH;
#pragma unroll
        for (int dj = 0; dj < 8; dj++) {
            int d = dj * 8 + (lane & 3) * 2;
            *(unsigned*)(ao + rowoff + d) =
                pkbf(o[dj][rr * 2] * inv, o[dj][rr * 2 + 1] * inv);
        }
    }
}

// ---------------- LayerNorm (torch semantics: ddof=1, /(std+eps)) ----------------
__global__ __launch_bounds__(256)
void layernorm_kernel(const float* __restrict__ in, const float* __restrict__ gamma,
                      const float* __restrict__ beta, float* __restrict__ out,
                      bf16* __restrict__ outH, bf16* __restrict__ outL)
{
    __shared__ float red[32];
    __shared__ float bc[2];
    const int row = blockIdx.x;
    const int tid = threadIdx.x;
    const int lane = tid & 31, wid = tid >> 5;

    float v[3];
    float s1 = 0.f;
#pragma unroll
    for (int t = 0; t < 3; t++) {
        v[t] = in[(size_t)row * D_MODEL + tid + t * 256];
        s1 += v[t];
    }
#pragma unroll
    for (int off = 16; off >= 1; off >>= 1) s1 += __shfl_xor_sync(0xffffffffu, s1, off);
    if (lane == 0) red[wid] = s1;
    __syncthreads();
    if (tid == 0) {
        float acc = 0.f;
        for (int w = 0; w < 8; w++) acc += red[w];
        bc[0] = acc / (float)D_MODEL;
    }
    __syncthreads();
    float mean = bc[0];

    float s2 = 0.f;
#pragma unroll
    for (int t = 0; t < 3; t++) {
        float d = v[t] - mean;
        s2 += d * d;
    }
#pragma unroll
    for (int off = 16; off >= 1; off >>= 1) s2 += __shfl_xor_sync(0xffffffffu, s2, off);
    if (lane == 0) red[wid] = s2;
    __syncthreads();
    if (tid == 0) {
        float acc = 0.f;
        for (int w = 0; w < 8; w++) acc += red[w];
        float var = acc / (float)(D_MODEL - 1);
        bc[1] = 1.f / (sqrtf(var) + LN_EPS);
    }
    __syncthreads();
    float inv = bc[1];

#pragma unroll
    for (int t = 0; t < 3; t++) {
        int c = tid + t * 256;
        float y = gamma[c] * (v[t] - mean) * inv + beta[c];
        out[(size_t)row * D_MODEL + c] = y;
        if (outH) {
            bf16 h = __float2bfloat16(y);
            outH[(size_t)row * D_MODEL + c] = h;
            outL[(size_t)row * D_MODEL + c] = __float2bfloat16(y - __bfloat162float(h));
        }
    }
}

// ---------------- launch ----------------
extern "C" void kernel_launch(void* const* d_in, const int* in_sizes, int n_in,
                              void* d_out, int out_size)
{
    const float* x   = (const float*)d_in[0];
    const void*  mraw = (const void*)d_in[1];
    const float* wq = (const float*)d_in[2];
    const float* bq = (const float*)d_in[3];
    const float* wk = (const float*)d_in[4];
    const float* bk = (const float*)d_in[5];
    const float* wv = (const float*)d_in[6];
    const float* bv = (const float*)d_in[7];
    const float* wo = (const float*)d_in[8];
    const float* bo = (const float*)d_in[9];
    const float* w1 = (const float*)d_in[10];
    const float* b1 = (const float*)d_in[11];
    const float* w2 = (const float*)d_in[12];
    const float* b2 = (const float*)d_in[13];
    const float* g1 = (const float*)d_in[14];
    const float* be1 = (const float*)d_in[15];
    const float* g2 = (const float*)d_in[16];
    const float* be2 = (const float*)d_in[17];
    float* outp = (float*)d_out;

    bf16 *xh, *wqh, *wkh, *wvh, *woh, *w1h, *w1l, *w2h, *w2l;
    bf16 *qh, *kh, *vh, *ah, *ffh, *ffl, *x1h, *x1l;
    float *res1, *x1, *res2;
    cudaGetSymbolAddress((void**)&xh,  g_xh);
    cudaGetSymbolAddress((void**)&wqh, g_wqh);
    cudaGetSymbolAddress((void**)&wkh, g_wkh);
    cudaGetSymbolAddress((void**)&wvh, g_wvh);
    cudaGetSymbolAddress((void**)&woh, g_woh);
    cudaGetSymbolAddress((void**)&w1h, g_w1h); cudaGetSymbolAddress((void**)&w1l, g_w1l);
    cudaGetSymbolAddress((void**)&w2h, g_w2h); cudaGetSymbolAddress((void**)&w2l, g_w2l);
    cudaGetSymbolAddress((void**)&qh,  g_qh);
    cudaGetSymbolAddress((void**)&kh,  g_kh);
    cudaGetSymbolAddress((void**)&vh,  g_vh);
    cudaGetSymbolAddress((void**)&ah,  g_ah);
    cudaGetSymbolAddress((void**)&ffh, g_ffh); cudaGetSymbolAddress((void**)&ffl, g_ffl);
    cudaGetSymbolAddress((void**)&x1h, g_x1h); cudaGetSymbolAddress((void**)&x1l, g_x1l);
    cudaGetSymbolAddress((void**)&res1, g_res1);
    cudaGetSymbolAddress((void**)&x1,   g_x1);
    cudaGetSymbolAddress((void**)&res2, g_res2);

    const int GSM1 = 2 * 20480;      // 40960 (single-pass gemm)
    const int GSM3 = 2 * 40960;      // 81920 (split gemm)
    const int ASM  = 2 * F_BUF;      // 37376
    cudaFuncSetAttribute((const void*)gemm_mma<EPI_QKV, 1>,  cudaFuncAttributeMaxDynamicSharedMemorySize, GSM1);
    cudaFuncSetAttribute((const void*)gemm_mma<EPI_ORES, 1>, cudaFuncAttributeMaxDynamicSharedMemorySize, GSM1);
    cudaFuncSetAttribute((const void*)gemm_mma<EPI_FF1, 3>,  cudaFuncAttributeMaxDynamicSharedMemorySize, GSM3);
    cudaFuncSetAttribute((const void*)gemm_mma<EPI_FF2, 3>,  cudaFuncAttributeMaxDynamicSharedMemorySize, GSM3);
    cudaFuncSetAttribute((const void*)flash_mma, cudaFuncAttributeMaxDynamicSharedMemorySize, ASM);

    dim3 blk(256);

    // mask + input/weight conversions
    mask_canon_kernel<<<1, 256>>>(mraw);
    cvt1<<<(MROWS * D_MODEL) / 1024, blk>>>(x, xh, MROWS * D_MODEL);
    cvt1<<<(D_MODEL * D_MODEL) / 1024, blk>>>(wq, wqh, D_MODEL * D_MODEL);
    cvt1<<<(D_MODEL * D_MODEL) / 1024, blk>>>(wk, wkh, D_MODEL * D_MODEL);
    cvt1<<<(D_MODEL * D_MODEL) / 1024, blk>>>(wv, wvh, D_MODEL * D_MODEL);
    cvt1<<<(D_MODEL * D_MODEL) / 1024, blk>>>(wo, woh, D_MODEL * D_MODEL);
    cvt_split<<<(DFF * D_MODEL) / 1024, blk>>>(w1, w1h, w1l, DFF * D_MODEL);
    cvt_split<<<(D_MODEL * DFF) / 1024, blk>>>(w2, w2h, w2l, D_MODEL * DFF);

    dim3 gP(MROWS / 128, D_MODEL / 128);   // (32, 6)
    dim3 gF1(MROWS / 128, DFF / 128);      // (32, 24)

    // QKV projections (single-pass bf16) → bf16 [b,h,s,d]
    gemm_mma<EPI_QKV, 1><<<gP, blk, GSM1>>>(xh, nullptr, wqh, nullptr, bq, nullptr, nullptr, qh, nullptr, D_MODEL, D_MODEL);
    gemm_mma<EPI_QKV, 1><<<gP, blk, GSM1>>>(xh, nullptr, wkh, nullptr, bk, nullptr, nullptr, kh, nullptr, D_MODEL, D_MODEL);
    gemm_mma<EPI_QKV, 1><<<gP, blk, GSM1>>>(xh, nullptr, wvh, nullptr, bv, nullptr, nullptr, vh, nullptr, D_MODEL, D_MODEL);

    // attention (single-pass bf16) → bf16 [m, 768]
    flash_mma<<<dim3(SEQ / 128, BHTOT), blk, ASM>>>(qh, kh, vh, ah);

    // O projection + residual(x) → res1 (single-pass); LN1 → x1 (fp32 + bf16 split)
    gemm_mma<EPI_ORES, 1><<<gP, blk, GSM1>>>(ah, nullptr, woh, nullptr, bo, x, res1, nullptr, nullptr, D_MODEL, D_MODEL);
    layernorm_kernel<<<MROWS, blk>>>(res1, g1, be1, x1, x1h, x1l);

    // FFN (3-mma split: accuracy-critical path)
    gemm_mma<EPI_FF1, 3><<<gF1, blk, GSM3>>>(x1h, x1l, w1h, w1l, b1, nullptr, nullptr, ffh, ffl, D_MODEL, DFF);
    gemm_mma<EPI_FF2, 3><<<gP, blk, GSM3>>>(ffh, ffl, w2h, w2l, b2, x1, res2, nullptr, nullptr, DFF, D_MODEL);
    layernorm_kernel<<<MROWS, blk>>>(res2, g2, be2, outp, nullptr, nullptr);
}

// round 11
// speedup vs baseline: 5.8650x; 1.0750x over previous
#include <cuda_runtime.h>
#include <cuda_bf16.h>
#include <cuda_fp16.h>

#define D_MODEL 768
#define NHEADS  12
#define DKH     64
#define SEQ     2048
#define BATCH   2
#define DFF     3072
#define MROWS   (BATCH*SEQ)          // 4096
#define BHTOT   (BATCH*NHEADS)       // 24
#define LN_EPS  1e-6f
#define QSCL    0.180336880111f      // 0.125 * log2(e)
#define MADDC   (-1.8033688e8f)      // -1e9 * QSCL (additive mask, exp2 domain)

typedef __nv_bfloat16 bf16;
typedef __nv_bfloat162 bf162;

// ---------------- scratch (static device memory, allowed) ----------------
__device__ __align__(16) bf16 g_xh   [MROWS*D_MODEL];
__device__ __align__(16) bf16 g_wqkvh[3*D_MODEL*D_MODEL];
__device__ __align__(16) bf16 g_woh  [D_MODEL*D_MODEL];
__device__ __align__(16) bf16 g_w1h  [DFF*D_MODEL];
__device__ __align__(16) bf16 g_w1l  [DFF*D_MODEL];
__device__ __align__(16) bf16 g_w2h  [D_MODEL*DFF];
__device__ __align__(16) bf16 g_w2l  [D_MODEL*DFF];
__device__ __align__(16) bf16 g_qh   [BHTOT*SEQ*DKH];
__device__ __align__(16) bf16 g_kh   [BHTOT*SEQ*DKH];
__device__ __align__(16) __half g_vhalf[BHTOT*SEQ*DKH];
__device__ __align__(16) bf16 g_ah   [MROWS*D_MODEL];
__device__ __align__(16) bf16 g_ffh  [MROWS*DFF];
__device__ __align__(16) bf16 g_ffl  [MROWS*DFF];
__device__ __align__(16) bf16 g_x1h  [MROWS*D_MODEL];
__device__ __align__(16) bf16 g_x1l  [MROWS*D_MODEL];
__device__ __align__(16) float g_res1[MROWS*D_MODEL];
__device__ __align__(16) float g_x1  [MROWS*D_MODEL];
__device__ __align__(16) float g_res2[MROWS*D_MODEL];
__device__ __align__(16) float g_maskf[BATCH*SEQ];   // additive: 0.0 keep, MADDC masked

// ---------------- asm helpers ----------------
__device__ __forceinline__ void ldsm4(unsigned* r, unsigned addr) {
    asm volatile("ldmatrix.sync.aligned.m8n8.x4.shared.b16 {%0,%1,%2,%3}, [%4];"
        : "=r"(r[0]), "=r"(r[1]), "=r"(r[2]), "=r"(r[3]) : "r"(addr));
}
__device__ __forceinline__ void ldsm4t(unsigned* r, unsigned addr) {
    asm volatile("ldmatrix.sync.aligned.m8n8.x4.trans.shared.b16 {%0,%1,%2,%3}, [%4];"
        : "=r"(r[0]), "=r"(r[1]), "=r"(r[2]), "=r"(r[3]) : "r"(addr));
}
__device__ __forceinline__ void mma16816(float* c, const unsigned* a, unsigned b0, unsigned b1) {
    asm volatile("mma.sync.aligned.m16n8k16.row.col.f32.bf16.bf16.f32 "
        "{%0,%1,%2,%3}, {%4,%5,%6,%7}, {%8,%9}, {%0,%1,%2,%3};"
        : "+f"(c[0]), "+f"(c[1]), "+f"(c[2]), "+f"(c[3])
        : "r"(a[0]), "r"(a[1]), "r"(a[2]), "r"(a[3]), "r"(b0), "r"(b1));
}
__device__ __forceinline__ void mma16816h(float* c, const unsigned* a, unsigned b0, unsigned b1) {
    asm volatile("mma.sync.aligned.m16n8k16.row.col.f32.f16.f16.f32 "
        "{%0,%1,%2,%3}, {%4,%5,%6,%7}, {%8,%9}, {%0,%1,%2,%3};"
        : "+f"(c[0]), "+f"(c[1]), "+f"(c[2]), "+f"(c[3])
        : "r"(a[0]), "r"(a[1]), "r"(a[2]), "r"(a[3]), "r"(b0), "r"(b1));
}
__device__ __forceinline__ void cp16(unsigned saddr, const void* gptr) {
    asm volatile("cp.async.ca.shared.global [%0], [%1], 16;" :: "r"(saddr), "l"(gptr));
}
__device__ __forceinline__ void cp_commit() { asm volatile("cp.async.commit_group;"); }
__device__ __forceinline__ void cp_wait1() { asm volatile("cp.async.wait_group 1;"); }
__device__ __forceinline__ void cp_wait0() { asm volatile("cp.async.wait_group 0;"); }

__device__ __forceinline__ unsigned pkbf(float a, float b) {
    bf162 t = __floats2bfloat162_rn(a, b);
    return reinterpret_cast<unsigned&>(t);
}
__device__ __forceinline__ unsigned pkhf(float a, float b) {
    __half2 t = __floats2half2_rn(a, b);
    return reinterpret_cast<unsigned&>(t);
}
__device__ __forceinline__ void split2(float e0, float e1, unsigned& h2, unsigned& l2) {
    bf162 h = __floats2bfloat162_rn(e0, e1);
    h2 = reinterpret_cast<unsigned&>(h);
    float f0 = __bfloat162float(h.x);
    float f1 = __bfloat162float(h.y);
    bf162 l = __floats2bfloat162_rn(e0 - f0, e1 - f1);
    l2 = reinterpret_cast<unsigned&>(l);
}
__device__ __forceinline__ unsigned long long pk2d(float lo, float hi) {
    unsigned long long r;
    asm("mov.b64 %0, {%1,%2};" : "=l"(r) : "f"(lo), "f"(hi));
    return r;
}
#define MULX2(d, a, b) asm("mul.rn.f32x2 %0, %1, %2;" : "=l"(d) : "l"(a), "l"(b))

// ---------------- mega convert (mask + all weight/input converts, 1 launch) ----
__device__ __forceinline__ void cvt1_body(const float* s, bf16* h, int lb, int tid) {
    int i = (lb * 256 + tid) * 4;
    float4 v = *(const float4*)(s + i);
    *(unsigned*)(h + i)     = pkbf(v.x, v.y);
    *(unsigned*)(h + i + 2) = pkbf(v.z, v.w);
}
__device__ __forceinline__ void split_body(const float* s, bf16* h, bf16* l, int lb, int tid) {
    int i = (lb * 256 + tid) * 4;
    float4 v = *(const float4*)(s + i);
    unsigned h01, l01, h23, l23;
    split2(v.x, v.y, h01, l01);
    split2(v.z, v.w, h23, l23);
    *(unsigned*)(h + i)     = h01;
    *(unsigned*)(h + i + 2) = h23;
    *(unsigned*)(l + i)     = l01;
    *(unsigned*)(l + i + 2) = l23;
}

__global__ __launch_bounds__(256)
void megacvt(const float* __restrict__ x, const float* __restrict__ wq,
             const float* __restrict__ wk, const float* __restrict__ wv,
             const float* __restrict__ wo, const float* __restrict__ w1,
             const float* __restrict__ w2, const void* __restrict__ mraw)
{
    const int b = blockIdx.x, tid = threadIdx.x;
    const int WSZ = D_MODEL * D_MODEL;           // 589824
    if (b < 3072)      cvt1_body(x,  g_xh, b, tid);
    else if (b < 3648) cvt1_body(wq, g_wqkvh,           b - 3072, tid);
    else if (b < 4224) cvt1_body(wk, g_wqkvh + WSZ,     b - 3648, tid);
    else if (b < 4800) cvt1_body(wv, g_wqkvh + 2 * WSZ, b - 4224, tid);
    else if (b < 5376) cvt1_body(wo, g_woh, b - 4800, tid);
    else if (b < 7680) split_body(w1, g_w1h, g_w1l, b - 5376, tid);
    else if (b < 9984) split_body(w2, g_w2h, g_w2l, b - 7680, tid);
    else {
        // mask canonicalization (single block): detect int32 vs uint8, write additive floats
        __shared__ int s_flag;
        const unsigned int* w = (const unsigned int*)mraw;
        if (tid == 0) s_flag = 0;
        __syncthreads();
        int any = 0;
        for (int i = tid; i < 1024; i += 256)
            if (w[i] > 1u) any = 1;
        if (any) atomicOr(&s_flag, 1);
        __syncthreads();
        if (s_flag) {
            const unsigned char* mb = (const unsigned char*)mraw;
            for (int i = tid; i < BATCH * SEQ; i += 256)
                g_maskf[i] = mb[i] ? MADDC : 0.0f;
        } else {
            const int* mi = (const int*)mraw;
            for (int i = tid; i < BATCH * SEQ; i += 256)
                g_maskf[i] = mi[i] ? MADDC : 0.0f;
        }
    }
}

// ---------------- tensor-core GEMM: C[m,n] = sum_k A[m,k]*W[n,k] ----------------
// block 128x128, ktile 32, 8 warps (warp tile 32m x 64n).
// SPLIT=3: bf16-split 3-mma. SPLIT=1: plain bf16.
enum { EPI_QKV = 0, EPI_ORES = 1, EPI_FF1 = 2, EPI_FF2 = 3 };

template<int EPI, int SPLIT>
__global__ __launch_bounds__(256, 2)
void gemm_mma(const bf16* __restrict__ Ah, const bf16* __restrict__ Al,
              const bf16* __restrict__ Wh, const bf16* __restrict__ Wl,
              const float* __restrict__ bias, const float* __restrict__ bias2,
              const float* __restrict__ bias3, const float* __restrict__ res,
              float* __restrict__ outF, bf16* __restrict__ outH, bf16* __restrict__ outL,
              __half* __restrict__ outV, int Kdim, int Ndim)
{
    const int WOFF  = (SPLIT == 3) ? 20480 : 10240;
    const int BUFSZ = (SPLIT == 3) ? 40960 : 20480;

    extern __shared__ char smem[];
    const unsigned sb = (unsigned)__cvta_generic_to_shared(smem);
    const int tid = threadIdx.x, lane = tid & 31, warp = tid >> 5;
    const int wm = warp & 3, wn = warp >> 2;
    const int m0 = blockIdx.x * 128, n0 = blockIdx.y * 128;

    const int lr = tid >> 1;
    const int lc = (tid & 1) * 2;
    const bf16* gAh = Ah + (size_t)(m0 + lr) * Kdim + lc * 8;
    const bf16* gWh = Wh + (size_t)(n0 + lr) * Kdim + lc * 8;
    const bf16* gAl = (SPLIT == 3) ? Al + (size_t)(m0 + lr) * Kdim + lc * 8 : nullptr;
    const bf16* gWl = (SPLIT == 3) ? Wl + (size_t)(n0 + lr) * Kdim + lc * 8 : nullptr;
    const unsigned st = lr * 80 + lc * 16;

    float acc[2][8][4] = {};
    const int nk = Kdim / 32;

    auto issue = [&](int kt, int buf) {
        unsigned b = sb + buf * BUFSZ;
        int ke = kt * 32;
#pragma unroll
        for (int c = 0; c < 2; c++) {
            cp16(b +        st + c * 16, gAh + ke + c * 8);
            cp16(b + WOFF + st + c * 16, gWh + ke + c * 8);
            if (SPLIT == 3) {
                cp16(b + 10240 +        st + c * 16, gAl + ke + c * 8);
                cp16(b + WOFF + 10240 + st + c * 16, gWl + ke + c * 8);
            }
        }
        cp_commit();
    };

    issue(0, 0);
    for (int kt = 0; kt < nk; kt++) {
        int buf = kt & 1;
        if (kt + 1 < nk) { issue(kt + 1, buf ^ 1); cp_wait1(); }
        else             { cp_wait0(); }
        __syncthreads();

        unsigned b = sb + buf * BUFSZ;
        const unsigned ar = lane & 15;
#pragma unroll
        for (int ks = 0; ks < 2; ks++) {
            const unsigned ac = ks * 2 + (lane >> 4);
            unsigned ah[2][4], al[2][4];
#pragma unroll
            for (int mi = 0; mi < 2; mi++) {
                unsigned addr = b + (wm * 32 + mi * 16 + ar) * 80 + ac * 16;
                ldsm4(ah[mi], addr);
                if (SPLIT == 3) ldsm4(al[mi], addr + 10240);
            }
#pragma unroll
            for (int ni2 = 0; ni2 < 4; ni2++) {
                unsigned bh[4], bl[4];
                unsigned addr = b + WOFF + (wn * 64 + ni2 * 16 + ar) * 80 + ac * 16;
                ldsm4(bh, addr);
                if (SPLIT == 3) ldsm4(bl, addr + 10240);
#pragma unroll
                for (int mi = 0; mi < 2; mi++) {
                    mma16816(acc[mi][ni2 * 2],     ah[mi], bh[0], bh[2]);
                    mma16816(acc[mi][ni2 * 2 + 1], ah[mi], bh[1], bh[3]);
                    if (SPLIT == 3) {
                        mma16816(acc[mi][ni2 * 2],     ah[mi], bl[0], bl[2]);
                        mma16816(acc[mi][ni2 * 2 + 1], ah[mi], bl[1], bl[3]);
                        mma16816(acc[mi][ni2 * 2],     al[mi], bh[0], bh[2]);
                        mma16816(acc[mi][ni2 * 2 + 1], al[mi], bh[1], bh[3]);
                    }
                }
            }
        }
        __syncthreads();
    }

    // epilogue
    const int sec = (EPI == EPI_QKV) ? (n0 / D_MODEL) : 0;   // 0=Q 1=K 2=V
    const float* bs = (EPI == EPI_QKV)
        ? (sec == 0 ? bias : (sec == 1 ? bias2 : bias3)) : bias;
#pragma unroll
    for (int mi = 0; mi < 2; mi++)
#pragma unroll
    for (int rr = 0; rr < 2; rr++) {
        int m = m0 + wm * 32 + mi * 16 + (lane >> 2) + rr * 8;
#pragma unroll
        for (int ni = 0; ni < 8; ni++) {
            int n = n0 + wn * 64 + ni * 8 + (lane & 3) * 2;
            float a0 = acc[mi][ni][rr * 2 + 0];
            float a1 = acc[mi][ni][rr * 2 + 1];
            if (EPI == EPI_QKV) {
                int nl = n - sec * D_MODEL;
                float v0 = a0 + bs[nl], v1 = a1 + bs[nl + 1];
                int b_ = m >> 11, s_ = m & (SEQ - 1);
                int h_ = nl >> 6, d_ = nl & 63;
                size_t idx = ((size_t)(b_ * NHEADS + h_) * SEQ + s_) * DKH + d_;
                if (sec == 0)      *(unsigned*)(outH + idx) = pkbf(v0 * QSCL, v1 * QSCL);
                else if (sec == 1) *(unsigned*)(outL + idx) = pkbf(v0, v1);
                else               *(unsigned*)(outV + idx) = pkhf(v0, v1);
            } else if (EPI == EPI_ORES || EPI == EPI_FF2) {
                float v0 = a0 + bs[n] + res[(size_t)m * Ndim + n];
                float v1 = a1 + bs[n + 1] + res[(size_t)m * Ndim + n + 1];
                outF[(size_t)m * Ndim + n]     = v0;
                outF[(size_t)m * Ndim + n + 1] = v1;
            } else { // EPI_FF1: relu + bf16 split
                float v0 = fmaxf(a0 + bs[n], 0.f);
                float v1 = fmaxf(a1 + bs[n + 1], 0.f);
                unsigned h2, l2;
                split2(v0, v1, h2, l2);
                size_t idx = (size_t)m * Ndim + n;
                *(unsigned*)(outH + idx) = h2;
                *(unsigned*)(outL + idx) = l2;
            }
        }
    }
}

// ---------------- flash attention: bf16 QK^T, f16x2-exp softmax, f16 PV -------
#define FK 0
#define FV 9216
#define FM 18432
#define F_BUF 18688

__global__ __launch_bounds__(256)
void flash_mma(const bf16* __restrict__ qm, const bf16* __restrict__ km,
               const __half* __restrict__ vm, bf16* __restrict__ ao)
{
    extern __shared__ char smem[];
    const unsigned sb = (unsigned)__cvta_generic_to_shared(smem);
    const int tid = threadIdx.x, lane = tid & 31, w = tid >> 5;
    const int bh = blockIdx.y;
    const int b_ = bh / NHEADS, h_ = bh % NHEADS;
    const int q0 = blockIdx.x * 128;

    unsigned qf[4][4];
    {
        int r = tid >> 2, cbq = (tid & 3) * 2;
#pragma unroll
        for (int p = 0; p < 2; p++) {
            const bf16* gq = qm + ((size_t)bh * SEQ + q0 + p * 64 + r) * DKH + cbq * 8;
            uint4 h0 = *(const uint4*)gq;
            uint4 h1 = *(const uint4*)(gq + 8);
            __syncthreads();
            *(uint4*)(smem + FK + r * 144 + cbq * 16)      = h0;
            *(uint4*)(smem + FK + r * 144 + cbq * 16 + 16) = h1;
            __syncthreads();
            if ((w >> 2) == p) {
                int lrow = (w - p * 4) * 16 + (lane & 15);
#pragma unroll
                for (int ks = 0; ks < 4; ks++) {
                    unsigned addr = sb + FK + lrow * 144 + (ks * 2 + (lane >> 4)) * 16;
                    ldsm4(qf[ks], addr);
                }
            }
        }
        __syncthreads();
    }

    const int r = tid >> 2, cb = (tid & 3) * 2;
    const bf16*   gK = km + ((size_t)bh * SEQ + r) * DKH + cb * 8;
    const __half* gV = vm + ((size_t)bh * SEQ + r) * DKH + cb * 8;
    const float* gM = g_maskf + b_ * SEQ;
    const unsigned st = r * 144 + cb * 16;

    auto issue = [&](int kt, int buf) {
        unsigned base = sb + buf * F_BUF;
        size_t ke = (size_t)kt * 64 * DKH;
#pragma unroll
        for (int c = 0; c < 2; c++) {
            cp16(base + FK + st + c * 16, gK + ke + c * 8);
            cp16(base + FV + st + c * 16, gV + ke + c * 8);
        }
        if (tid < 16) cp16(base + FM + tid * 16, gM + kt * 64 + tid * 4);
        cp_commit();
    };

    __align__(16) float o[8][4] = {};
    float mi[2] = {-1e30f, -1e30f};
    float li[2] = {0.f, 0.f};

    issue(0, 0);
    const int NT = SEQ / 64;
    for (int kt = 0; kt < NT; kt++) {
        int buf = kt & 1;
        unsigned base = sb + buf * F_BUF;
        if (kt + 1 < NT) { issue(kt + 1, buf ^ 1); cp_wait1(); }
        else             { cp_wait0(); }
        __syncthreads();

        // S = Q K^T (exp2-domain: Q pre-scaled by 0.125*log2e)
        float s[8][4] = {};
        const unsigned ar = lane & 15;
#pragma unroll
        for (int ks = 0; ks < 4; ks++) {
            const unsigned ac = ks * 2 + (lane >> 4);
#pragma unroll
            for (int ni2 = 0; ni2 < 4; ni2++) {
                unsigned kr[4];
                ldsm4(kr, base + FK + (ni2 * 16 + ar) * 144 + ac * 16);
                mma16816(s[ni2 * 2],     qf[ks], kr[0], kr[2]);
                mma16816(s[ni2 * 2 + 1], qf[ks], kr[1], kr[3]);
            }
        }

        // additive mask (0 or -1.8e8) for this thread's 16 columns
        const float* msk = (const float*)(smem + buf * F_BUF + FM);
        float madd[16];
#pragma unroll
        for (int ni = 0; ni < 8; ni++) {
            int col = ni * 8 + (lane & 3) * 2;
            madd[ni * 2]     = msk[col];
            madd[ni * 2 + 1] = msk[col + 1];
        }

        unsigned pf[8][2];   // P fragments as f16x2, [ni][rr]
#pragma unroll
        for (int rr = 0; rr < 2; rr++) {
            float rmax = -1e30f;
#pragma unroll
            for (int ni = 0; ni < 8; ni++)
#pragma unroll
                for (int jj = 0; jj < 2; jj++) {
                    float xx = s[ni][rr * 2 + jj] + madd[ni * 2 + jj];
                    s[ni][rr * 2 + jj] = xx;
                    rmax = fmaxf(rmax, xx);
                }
            rmax = fmaxf(rmax, __shfl_xor_sync(0xffffffffu, rmax, 1));
            rmax = fmaxf(rmax, __shfl_xor_sync(0xffffffffu, rmax, 2));
            float mnew = fmaxf(mi[rr], rmax);
            float fac = exp2f(mi[rr] - mnew);
            float rsum = 0.f;
#pragma unroll
            for (int ni = 0; ni < 8; ni++) {
                unsigned hp = pkhf(s[ni][rr * 2] - mnew, s[ni][rr * 2 + 1] - mnew);
                unsigned pe;
                asm("ex2.approx.f16x2 %0, %1;" : "=r"(pe) : "r"(hp));
                pf[ni][rr] = pe;
                __half2 pv = reinterpret_cast<__half2&>(pe);
                float2 pg = __half22float2(pv);
                rsum += pg.x + pg.y;
            }
            rsum += __shfl_xor_sync(0xffffffffu, rsum, 1);
            rsum += __shfl_xor_sync(0xffffffffu, rsum, 2);
            li[rr] = li[rr] * fac + rsum;
            mi[rr] = mnew;
            unsigned long long fp = pk2d(fac, fac);
            unsigned long long* op = (unsigned long long*)o;
#pragma unroll
            for (int dj = 0; dj < 8; dj++)
                MULX2(op[dj * 2 + rr], op[dj * 2 + rr], fp);
        }

        // O += P V (f16 x f16)
#pragma unroll
        for (int kk = 0; kk < 4; kk++) {
            unsigned ph[4] = { pf[2 * kk][0], pf[2 * kk][1],
                               pf[2 * kk + 1][0], pf[2 * kk + 1][1] };
            int g = lane >> 3;
            int vrow = kk * 16 + (g & 1) * 8 + (lane & 7);
#pragma unroll
            for (int dj2 = 0; dj2 < 4; dj2++) {
                int dcol = dj2 * 16 + (g >> 1) * 8;
                unsigned vr[4];
                ldsm4t(vr, base + FV + vrow * 144 + dcol * 2);
                mma16816h(o[dj2 * 2],     ph, vr[0], vr[1]);
                mma16816h(o[dj2 * 2 + 1], ph, vr[2], vr[3]);
            }
        }
        __syncthreads();
    }

#pragma unroll
    for (int rr = 0; rr < 2; rr++) {
        int qrow = q0 + w * 16 + (lane >> 2) + rr * 8;
        float inv = 1.f / li[rr];
        size_t rowoff = ((size_t)(b_ * SEQ + qrow)) * D_MODEL + h_ * DKH;
#pragma unroll
        for (int dj = 0; dj < 8; dj++) {
            int d = dj * 8 + (lane & 3) * 2;
            *(unsigned*)(ao + rowoff + d) =
                pkbf(o[dj][rr * 2] * inv, o[dj][rr * 2 + 1] * inv);
        }
    }
}

// ---------------- LayerNorm (torch semantics: ddof=1, /(std+eps)) ----------------
__global__ __launch_bounds__(256)
void layernorm_kernel(const float* __restrict__ in, const float* __restrict__ gamma,
                      const float* __restrict__ beta, float* __restrict__ out,
                      bf16* __restrict__ outH, bf16* __restrict__ outL)
{
    __shared__ float red[32];
    __shared__ float bc[2];
    const int row = blockIdx.x;
    const int tid = threadIdx.x;
    const int lane = tid & 31, wid = tid >> 5;

    float v[3];
    float s1 = 0.f;
#pragma unroll
    for (int t = 0; t < 3; t++) {
        v[t] = in[(size_t)row * D_MODEL + tid + t * 256];
        s1 += v[t];
    }
#pragma unroll
    for (int off = 16; off >= 1; off >>= 1) s1 += __shfl_xor_sync(0xffffffffu, s1, off);
    if (lane == 0) red[wid] = s1;
    __syncthreads();
    if (tid == 0) {
        float acc = 0.f;
        for (int w = 0; w < 8; w++) acc += red[w];
        bc[0] = acc / (float)D_MODEL;
    }
    __syncthreads();
    float mean = bc[0];

    float s2 = 0.f;
#pragma unroll
    for (int t = 0; t < 3; t++) {
        float d = v[t] - mean;
        s2 += d * d;
    }
#pragma unroll
    for (int off = 16; off >= 1; off >>= 1) s2 += __shfl_xor_sync(0xffffffffu, s2, off);
    if (lane == 0) red[wid] = s2;
    __syncthreads();
    if (tid == 0) {
        float acc = 0.f;
        for (int w = 0; w < 8; w++) acc += red[w];
        float var = acc / (float)(D_MODEL - 1);
        bc[1] = 1.f / (sqrtf(var) + LN_EPS);
    }
    __syncthreads();
    float inv = bc[1];

#pragma unroll
    for (int t = 0; t < 3; t++) {
        int c = tid + t * 256;
        float y = gamma[c] * (v[t] - mean) * inv + beta[c];
        out[(size_t)row * D_MODEL + c] = y;
        if (outH) {
            bf16 h = __float2bfloat16(y);
            outH[(size_t)row * D_MODEL + c] = h;
            outL[(size_t)row * D_MODEL + c] = __float2bfloat16(y - __bfloat162float(h));
        }
    }
}

// ---------------- launch ----------------
extern "C" void kernel_launch(void* const* d_in, const int* in_sizes, int n_in,
                              void* d_out, int out_size)
{
    const float* x   = (const float*)d_in[0];
    const void*  mraw = (const void*)d_in[1];
    const float* wq = (const float*)d_in[2];
    const float* bq = (const float*)d_in[3];
    const float* wk = (const float*)d_in[4];
    const float* bk = (const float*)d_in[5];
    const float* wv = (const float*)d_in[6];
    const float* bv = (const float*)d_in[7];
    const float* wo = (const float*)d_in[8];
    const float* bo = (const float*)d_in[9];
    const float* w1 = (const float*)d_in[10];
    const float* b1 = (const float*)d_in[11];
    const float* w2 = (const float*)d_in[12];
    const float* b2 = (const float*)d_in[13];
    const float* g1 = (const float*)d_in[14];
    const float* be1 = (const float*)d_in[15];
    const float* g2 = (const float*)d_in[16];
    const float* be2 = (const float*)d_in[17];
    float* outp = (float*)d_out;

    bf16 *xh, *wqkvh, *woh, *w1h, *w1l, *w2h, *w2l;
    bf16 *qh, *kh, *ah, *ffh, *ffl, *x1h, *x1l;
    __half *vh;
    float *res1, *x1, *res2;
    cudaGetSymbolAddress((void**)&xh,    g_xh);
    cudaGetSymbolAddress((void**)&wqkvh, g_wqkvh);
    cudaGetSymbolAddress((void**)&woh,   g_woh);
    cudaGetSymbolAddress((void**)&w1h, g_w1h); cudaGetSymbolAddress((void**)&w1l, g_w1l);
    cudaGetSymbolAddress((void**)&w2h, g_w2h); cudaGetSymbolAddress((void**)&w2l, g_w2l);
    cudaGetSymbolAddress((void**)&qh,  g_qh);
    cudaGetSymbolAddress((void**)&kh,  g_kh);
    cudaGetSymbolAddress((void**)&vh,  g_vhalf);
    cudaGetSymbolAddress((void**)&ah,  g_ah);
    cudaGetSymbolAddress((void**)&ffh, g_ffh); cudaGetSymbolAddress((void**)&ffl, g_ffl);
    cudaGetSymbolAddress((void**)&x1h, g_x1h); cudaGetSymbolAddress((void**)&x1l, g_x1l);
    cudaGetSymbolAddress((void**)&res1, g_res1);
    cudaGetSymbolAddress((void**)&x1,   g_x1);
    cudaGetSymbolAddress((void**)&res2, g_res2);

    const int GSM1 = 2 * 20480;
    const int GSM3 = 2 * 40960;
    const int ASM  = 2 * F_BUF;
    cudaFuncSetAttribute((const void*)gemm_mma<EPI_QKV, 1>,  cudaFuncAttributeMaxDynamicSharedMemorySize, GSM1);
    cudaFuncSetAttribute((const void*)gemm_mma<EPI_ORES, 1>, cudaFuncAttributeMaxDynamicSharedMemorySize, GSM1);
    cudaFuncSetAttribute((const void*)gemm_mma<EPI_FF1, 3>,  cudaFuncAttributeMaxDynamicSharedMemorySize, GSM3);
    cudaFuncSetAttribute((const void*)gemm_mma<EPI_FF2, 3>,  cudaFuncAttributeMaxDynamicSharedMemorySize, GSM3);
    cudaFuncSetAttribute((const void*)flash_mma, cudaFuncAttributeMaxDynamicSharedMemorySize, ASM);

    dim3 blk(256);

    // 1 launch: all converts + mask
    megacvt<<<9985, blk>>>(x, wq, wk, wv, wo, w1, w2, mraw);

    dim3 gQKV(MROWS / 128, 3 * D_MODEL / 128);   // (32, 18)
    dim3 gP(MROWS / 128, D_MODEL / 128);         // (32, 6)
    dim3 gF1(MROWS / 128, DFF / 128);            // (32, 24)

    // merged QKV projection: Q (scaled bf16), K (bf16), V (fp16)
    gemm_mma<EPI_QKV, 1><<<gQKV, blk, GSM1>>>(xh, nullptr, wqkvh, nullptr,
        bq, bk, bv, nullptr, nullptr, qh, kh, vh, D_MODEL, 3 * D_MODEL);

    // attention
    flash_mma<<<dim3(SEQ / 128, BHTOT), blk, ASM>>>(qh, kh, vh, ah);

    // O projection + residual(x) → res1; LN1 → x1 (fp32 + bf16 split)
    gemm_mma<EPI_ORES, 1><<<gP, blk, GSM1>>>(ah, nullptr, woh, nullptr,
        bo, nullptr, nullptr, x, res1, nullptr, nullptr, nullptr, D_MODEL, D_MODEL);
    layernorm_kernel<<<MROWS, blk>>>(res1, g1, be1, x1, x1h, x1l);

    // FFN (3-mma split: accuracy-critical path)
    gemm_mma<EPI_FF1, 3><<<gF1, blk, GSM3>>>(x1h, x1l, w1h, w1l,
        b1, nullptr, nullptr, nullptr, nullptr, ffh, ffl, nullptr, D_MODEL, DFF);
    gemm_mma<EPI_FF2, 3><<<gP, blk, GSM3>>>(ffh, ffl, w2h, w2l,
        b2, nullptr, nullptr, x1, res2, nullptr, nullptr, nullptr, DFF, D_MODEL);
    layernorm_kernel<<<MROWS, blk>>>(res2, g2, be2, outp, nullptr, nullptr);
}

// round 13
// speedup vs baseline: 10.3493x; 1.7646x over previous
#include <cuda_runtime.h>
#include <cuda_bf16.h>
#include <cuda_fp16.h>

#define D_MODEL 768
#define NHEADS  12
#define DKH     64
#define SEQ     2048
#define BATCH   2
#define DFF     3072
#define MROWS   (BATCH*SEQ)          // 4096
#define BHTOT   (BATCH*NHEADS)       // 24
#define LN_EPS  1e-6f
#define QSCL    0.180336880111f      // 0.125 * log2(e)
#define MADDC   (-1.8033688e8f)      // -1e9 * QSCL (additive mask, exp2 domain)

typedef __nv_bfloat16 bf16;
typedef __nv_bfloat162 bf162;

// ---------------- scratch (static device memory, allowed) ----------------
__device__ __align__(16) __half g_xh   [MROWS*D_MODEL];
__device__ __align__(16) __half g_wqkvh[3*D_MODEL*D_MODEL];
__device__ __align__(16) __half g_woh  [D_MODEL*D_MODEL];
__device__ __align__(16) __half g_w1h  [DFF*D_MODEL];
__device__ __align__(16) __half g_w2h  [D_MODEL*DFF];
__device__ __align__(16) __half g_qh   [BHTOT*SEQ*DKH];
__device__ __align__(16) __half g_kh   [BHTOT*SEQ*DKH];
__device__ __align__(16) __half g_vh   [BHTOT*SEQ*DKH];
__device__ __align__(16) __half g_ah   [MROWS*D_MODEL];
__device__ __align__(16) __half g_ffh  [MROWS*DFF];
__device__ __align__(16) __half g_x1h  [MROWS*D_MODEL];
__device__ __align__(16) float g_res1[MROWS*D_MODEL];
__device__ __align__(16) float g_x1  [MROWS*D_MODEL];
__device__ __align__(16) float g_res2[MROWS*D_MODEL];
__device__ __align__(16) float g_maskf[BATCH*SEQ];   // additive: 0.0 keep, MADDC masked

// ---------------- asm helpers ----------------
__device__ __forceinline__ void ldsm4(unsigned* r, unsigned addr) {
    asm volatile("ldmatrix.sync.aligned.m8n8.x4.shared.b16 {%0,%1,%2,%3}, [%4];"
        : "=r"(r[0]), "=r"(r[1]), "=r"(r[2]), "=r"(r[3]) : "r"(addr));
}
__device__ __forceinline__ void ldsm4t(unsigned* r, unsigned addr) {
    asm volatile("ldmatrix.sync.aligned.m8n8.x4.trans.shared.b16 {%0,%1,%2,%3}, [%4];"
        : "=r"(r[0]), "=r"(r[1]), "=r"(r[2]), "=r"(r[3]) : "r"(addr));
}
__device__ __forceinline__ void mma16816h(float* c, const unsigned* a, unsigned b0, unsigned b1) {
    asm volatile("mma.sync.aligned.m16n8k16.row.col.f32.f16.f16.f32 "
        "{%0,%1,%2,%3}, {%4,%5,%6,%7}, {%8,%9}, {%0,%1,%2,%3};"
        : "+f"(c[0]), "+f"(c[1]), "+f"(c[2]), "+f"(c[3])
        : "r"(a[0]), "r"(a[1]), "r"(a[2]), "r"(a[3]), "r"(b0), "r"(b1));
}
__device__ __forceinline__ void cp16(unsigned saddr, const void* gptr) {
    asm volatile("cp.async.ca.shared.global [%0], [%1], 16;" :: "r"(saddr), "l"(gptr));
}
__device__ __forceinline__ void cp_commit() { asm volatile("cp.async.commit_group;"); }
__device__ __forceinline__ void cp_wait1() { asm volatile("cp.async.wait_group 1;"); }
__device__ __forceinline__ void cp_wait0() { asm volatile("cp.async.wait_group 0;"); }

__device__ __forceinline__ unsigned pkbf(float a, float b) {
    bf162 t = __floats2bfloat162_rn(a, b);
    return reinterpret_cast<unsigned&>(t);
}
__device__ __forceinline__ unsigned pkhf(float a, float b) {
    __half2 t = __floats2half2_rn(a, b);
    return reinterpret_cast<unsigned&>(t);
}
__device__ __forceinline__ unsigned long long pk2d(float lo, float hi) {
    unsigned long long r;
    asm("mov.b64 %0, {%1,%2};" : "=l"(r) : "f"(lo), "f"(hi));
    return r;
}
#define MULX2(d, a, b) asm("mul.rn.f32x2 %0, %1, %2;" : "=l"(d) : "l"(a), "l"(b))

// ---------------- mega convert (mask + all weight/input converts, 1 launch) ----
__device__ __forceinline__ void cvt_h(const float* s, __half* h, int lb, int tid) {
    int i = (lb * 256 + tid) * 4;
    float4 v = *(const float4*)(s + i);
    *(unsigned*)(h + i)     = pkhf(v.x, v.y);
    *(unsigned*)(h + i + 2) = pkhf(v.z, v.w);
}

__global__ __launch_bounds__(256)
void megacvt(const float* __restrict__ x, const float* __restrict__ wq,
             const float* __restrict__ wk, const float* __restrict__ wv,
             const float* __restrict__ wo, const float* __restrict__ w1,
             const float* __restrict__ w2, const void* __restrict__ mraw)
{
    const int b = blockIdx.x, tid = threadIdx.x;
    const int WSZ = D_MODEL * D_MODEL;           // 589824
    if (b < 3072)      cvt_h(x,  g_xh, b, tid);
    else if (b < 3648) cvt_h(wq, g_wqkvh,           b - 3072, tid);
    else if (b < 4224) cvt_h(wk, g_wqkvh + WSZ,     b - 3648, tid);
    else if (b < 4800) cvt_h(wv, g_wqkvh + 2 * WSZ, b - 4224, tid);
    else if (b < 5376) cvt_h(wo, g_woh, b - 4800, tid);
    else if (b < 7680) cvt_h(w1, g_w1h, b - 5376, tid);
    else if (b < 9984) cvt_h(w2, g_w2h, b - 7680, tid);
    else {
        // mask canonicalization (single block): detect int32 vs uint8, write additive floats
        __shared__ int s_flag;
        const unsigned int* w = (const unsigned int*)mraw;
        if (tid == 0) s_flag = 0;
        __syncthreads();
        int any = 0;
        for (int i = tid; i < 1024; i += 256)
            if (w[i] > 1u) any = 1;
        if (any) atomicOr(&s_flag, 1);
        __syncthreads();
        if (s_flag) {
            const unsigned char* mb = (const unsigned char*)mraw;
            for (int i = tid; i < BATCH * SEQ; i += 256)
                g_maskf[i] = mb[i] ? MADDC : 0.0f;
        } else {
            const int* mi = (const int*)mraw;
            for (int i = tid; i < BATCH * SEQ; i += 256)
                g_maskf[i] = mi[i] ? MADDC : 0.0f;
        }
    }
}

// ---------------- tensor-core GEMM (fp16 single-pass): C = A @ W^T ------------
// block 128x128, ktile 32, 8 warps (warp tile 32m x 64n).
enum { EPI_QKV = 0, EPI_ORES = 1, EPI_FF1 = 2, EPI_FF2 = 3 };

#define GWOFF 10240
#define GBUF  20480

template<int EPI>
__global__ __launch_bounds__(256, 2)
void gemm_mma(const __half* __restrict__ Ah, const __half* __restrict__ Wh,
              const float* __restrict__ bias, const float* __restrict__ bias2,
              const float* __restrict__ bias3, const float* __restrict__ res,
              float* __restrict__ outF, __half* __restrict__ outQ,
              __half* __restrict__ outK, __half* __restrict__ outV,
              int Kdim, int Ndim)
{
    extern __shared__ char smem[];
    const unsigned sb = (unsigned)__cvta_generic_to_shared(smem);
    const int tid = threadIdx.x, lane = tid & 31, warp = tid >> 5;
    const int wm = warp & 3, wn = warp >> 2;
    const int m0 = blockIdx.x * 128, n0 = blockIdx.y * 128;

    const int lr = tid >> 1;
    const int lc = (tid & 1) * 2;
    const __half* gAh = Ah + (size_t)(m0 + lr) * Kdim + lc * 8;
    const __half* gWh = Wh + (size_t)(n0 + lr) * Kdim + lc * 8;
    const unsigned st = lr * 80 + lc * 16;

    float acc[2][8][4] = {};
    const int nk = Kdim / 32;

    auto issue = [&](int kt, int buf) {
        unsigned b = sb + buf * GBUF;
        int ke = kt * 32;
#pragma unroll
        for (int c = 0; c < 2; c++) {
            cp16(b +         st + c * 16, gAh + ke + c * 8);
            cp16(b + GWOFF + st + c * 16, gWh + ke + c * 8);
        }
        cp_commit();
    };

    issue(0, 0);
    for (int kt = 0; kt < nk; kt++) {
        int buf = kt & 1;
        if (kt + 1 < nk) { issue(kt + 1, buf ^ 1); cp_wait1(); }
        else             { cp_wait0(); }
        __syncthreads();

        unsigned b = sb + buf * GBUF;
        const unsigned ar = lane & 15;
#pragma unroll
        for (int ks = 0; ks < 2; ks++) {
            const unsigned ac = ks * 2 + (lane >> 4);
            unsigned ah[2][4];
#pragma unroll
            for (int mi = 0; mi < 2; mi++)
                ldsm4(ah[mi], b + (wm * 32 + mi * 16 + ar) * 80 + ac * 16);
#pragma unroll
            for (int ni2 = 0; ni2 < 4; ni2++) {
                unsigned bh[4];
                ldsm4(bh, b + GWOFF + (wn * 64 + ni2 * 16 + ar) * 80 + ac * 16);
#pragma unroll
                for (int mi = 0; mi < 2; mi++) {
                    mma16816h(acc[mi][ni2 * 2],     ah[mi], bh[0], bh[2]);
                    mma16816h(acc[mi][ni2 * 2 + 1], ah[mi], bh[1], bh[3]);
                }
            }
        }
        __syncthreads();
    }

    // epilogue
    const int sec = (EPI == EPI_QKV) ? (n0 / D_MODEL) : 0;   // 0=Q 1=K 2=V
    const float* bs = (EPI == EPI_QKV)
        ? (sec == 0 ? bias : (sec == 1 ? bias2 : bias3)) : bias;
#pragma unroll
    for (int mi = 0; mi < 2; mi++)
#pragma unroll
    for (int rr = 0; rr < 2; rr++) {
        int m = m0 + wm * 32 + mi * 16 + (lane >> 2) + rr * 8;
#pragma unroll
        for (int ni = 0; ni < 8; ni++) {
            int n = n0 + wn * 64 + ni * 8 + (lane & 3) * 2;
            float a0 = acc[mi][ni][rr * 2 + 0];
            float a1 = acc[mi][ni][rr * 2 + 1];
            if (EPI == EPI_QKV) {
                int nl = n - sec * D_MODEL;
                float v0 = a0 + bs[nl], v1 = a1 + bs[nl + 1];
                int b_ = m >> 11, s_ = m & (SEQ - 1);
                int h_ = nl >> 6, d_ = nl & 63;
                size_t idx = ((size_t)(b_ * NHEADS + h_) * SEQ + s_) * DKH + d_;
                if (sec == 0)      *(unsigned*)(outQ + idx) = pkhf(v0 * QSCL, v1 * QSCL);
                else if (sec == 1) *(unsigned*)(outK + idx) = pkhf(v0, v1);
                else               *(unsigned*)(outV + idx) = pkhf(v0, v1);
            } else if (EPI == EPI_ORES || EPI == EPI_FF2) {
                float v0 = a0 + bs[n] + res[(size_t)m * Ndim + n];
                float v1 = a1 + bs[n + 1] + res[(size_t)m * Ndim + n + 1];
                outF[(size_t)m * Ndim + n]     = v0;
                outF[(size_t)m * Ndim + n + 1] = v1;
            } else { // EPI_FF1: relu, fp16 out
                float v0 = fmaxf(a0 + bs[n], 0.f);
                float v1 = fmaxf(a1 + bs[n + 1], 0.f);
                *(unsigned*)(outQ + (size_t)m * Ndim + n) = pkhf(v0, v1);
            }
        }
    }
}

// ---------------- flash attention: fp16 QK^T, f16x2-exp softmax, f16 PV -------
#define FK 0
#define FV 9216
#define FM 18432
#define F_BUF 18688

__global__ __launch_bounds__(256)
void flash_mma(const __half* __restrict__ qm, const __half* __restrict__ km,
               const __half* __restrict__ vm, __half* __restrict__ ao)
{
    extern __shared__ char smem[];
    const unsigned sb = (unsigned)__cvta_generic_to_shared(smem);
    const int tid = threadIdx.x, lane = tid & 31, w = tid >> 5;
    const int bh = blockIdx.y;
    const int b_ = bh / NHEADS, h_ = bh % NHEADS;
    const int q0 = blockIdx.x * 128;

    unsigned qf[4][4];
    {
        int r = tid >> 2, cbq = (tid & 3) * 2;
#pragma unroll
        for (int p = 0; p < 2; p++) {
            const __half* gq = qm + ((size_t)bh * SEQ + q0 + p * 64 + r) * DKH + cbq * 8;
            uint4 h0 = *(const uint4*)gq;
            uint4 h1 = *(const uint4*)(gq + 8);
            __syncthreads();
            *(uint4*)(smem + FK + r * 144 + cbq * 16)      = h0;
            *(uint4*)(smem + FK + r * 144 + cbq * 16 + 16) = h1;
            __syncthreads();
            if ((w >> 2) == p) {
                int lrow = (w - p * 4) * 16 + (lane & 15);
#pragma unroll
                for (int ks = 0; ks < 4; ks++) {
                    unsigned addr = sb + FK + lrow * 144 + (ks * 2 + (lane >> 4)) * 16;
                    ldsm4(qf[ks], addr);
                }
            }
        }
        __syncthreads();
    }

    const int r = tid >> 2, cb = (tid & 3) * 2;
    const __half* gK = km + ((size_t)bh * SEQ + r) * DKH + cb * 8;
    const __half* gV = vm + ((size_t)bh * SEQ + r) * DKH + cb * 8;
    const float* gM = g_maskf + b_ * SEQ;
    const unsigned st = r * 144 + cb * 16;

    auto issue = [&](int kt, int buf) {
        unsigned base = sb + buf * F_BUF;
        size_t ke = (size_t)kt * 64 * DKH;
#pragma unroll
        for (int c = 0; c < 2; c++) {
            cp16(base + FK + st + c * 16, gK + ke + c * 8);
            cp16(base + FV + st + c * 16, gV + ke + c * 8);
        }
        if (tid < 16) cp16(base + FM + tid * 16, gM + kt * 64 + tid * 4);
        cp_commit();
    };

    __align__(16) float o[8][4] = {};
    float mi[2] = {-1e30f, -1e30f};
    float li[2] = {0.f, 0.f};

    issue(0, 0);
    const int NT = SEQ / 64;
    for (int kt = 0; kt < NT; kt++) {
        int buf = kt & 1;
        unsigned base = sb + buf * F_BUF;
        if (kt + 1 < NT) { issue(kt + 1, buf ^ 1); cp_wait1(); }
        else             { cp_wait0(); }
        __syncthreads();

        // S = Q K^T (exp2-domain: Q pre-scaled by 0.125*log2e)
        float s[8][4] = {};
        const unsigned ar = lane & 15;
#pragma unroll
        for (int ks = 0; ks < 4; ks++) {
            const unsigned ac = ks * 2 + (lane >> 4);
#pragma unroll
            for (int ni2 = 0; ni2 < 4; ni2++) {
                unsigned kr[4];
                ldsm4(kr, base + FK + (ni2 * 16 + ar) * 144 + ac * 16);
                mma16816h(s[ni2 * 2],     qf[ks], kr[0], kr[2]);
                mma16816h(s[ni2 * 2 + 1], qf[ks], kr[1], kr[3]);
            }
        }

        // additive mask (0 or -1.8e8) for this thread's 16 columns
        const float* msk = (const float*)(smem + buf * F_BUF + FM);
        float madd[16];
#pragma unroll
        for (int ni = 0; ni < 8; ni++) {
            int col = ni * 8 + (lane & 3) * 2;
            madd[ni * 2]     = msk[col];
            madd[ni * 2 + 1] = msk[col + 1];
        }

        unsigned pf[8][2];   // P fragments as f16x2, [ni][rr]
#pragma unroll
        for (int rr = 0; rr < 2; rr++) {
            float rmax = -1e30f;
#pragma unroll
            for (int ni = 0; ni < 8; ni++)
#pragma unroll
                for (int jj = 0; jj < 2; jj++) {
                    float xx = s[ni][rr * 2 + jj] + madd[ni * 2 + jj];
                    s[ni][rr * 2 + jj] = xx;
                    rmax = fmaxf(rmax, xx);
                }
            rmax = fmaxf(rmax, __shfl_xor_sync(0xffffffffu, rmax, 1));
            rmax = fmaxf(rmax, __shfl_xor_sync(0xffffffffu, rmax, 2));
            float mnew = fmaxf(mi[rr], rmax);
            float fac = exp2f(mi[rr] - mnew);
            float rsum = 0.f;
#pragma unroll
            for (int ni = 0; ni < 8; ni++) {
                unsigned hp = pkhf(s[ni][rr * 2] - mnew, s[ni][rr * 2 + 1] - mnew);
                unsigned pe;
                asm("ex2.approx.f16x2 %0, %1;" : "=r"(pe) : "r"(hp));
                pf[ni][rr] = pe;
                __half2 pv = reinterpret_cast<__half2&>(pe);
                float2 pg = __half22float2(pv);
                rsum += pg.x + pg.y;
            }
            rsum += __shfl_xor_sync(0xffffffffu, rsum, 1);
            rsum += __shfl_xor_sync(0xffffffffu, rsum, 2);
            li[rr] = li[rr] * fac + rsum;
            mi[rr] = mnew;
            unsigned long long fp = pk2d(fac, fac);
            unsigned long long* op = (unsigned long long*)o;
#pragma unroll
            for (int dj = 0; dj < 8; dj++)
                MULX2(op[dj * 2 + rr], op[dj * 2 + rr], fp);
        }

        // O += P V (f16 x f16)
#pragma unroll
        for (int kk = 0; kk < 4; kk++) {
            unsigned ph[4] = { pf[2 * kk][0], pf[2 * kk][1],
                               pf[2 * kk + 1][0], pf[2 * kk + 1][1] };
            int g = lane >> 3;
            int vrow = kk * 16 + (g & 1) * 8 + (lane & 7);
#pragma unroll
            for (int dj2 = 0; dj2 < 4; dj2++) {
                int dcol = dj2 * 16 + (g >> 1) * 8;
                unsigned vr[4];
                ldsm4t(vr, base + FV + vrow * 144 + dcol * 2);
                mma16816h(o[dj2 * 2],     ph, vr[0], vr[1]);
                mma16816h(o[dj2 * 2 + 1], ph, vr[2], vr[3]);
            }
        }
        __syncthreads();
    }

#pragma unroll
    for (int rr = 0; rr < 2; rr++) {
        int qrow = q0 + w * 16 + (lane >> 2) + rr * 8;
        float inv = 1.f / li[rr];
        size_t rowoff = ((size_t)(b_ * SEQ + qrow)) * D_MODEL + h_ * DKH;
#pragma unroll
        for (int dj = 0; dj < 8; dj++) {
            int d = dj * 8 + (lane & 3) * 2;
            *(unsigned*)(ao + rowoff + d) =
                pkhf(o[dj][rr * 2] * inv, o[dj][rr * 2 + 1] * inv);
        }
    }
}

// ---------------- LayerNorm (torch semantics: ddof=1, /(std+eps)) ----------------
__global__ __launch_bounds__(256)
void layernorm_kernel(const float* __restrict__ in, const float* __restrict__ gamma,
                      const float* __restrict__ beta, float* __restrict__ out,
                      __half* __restrict__ outH)
{
    __shared__ float red[32];
    __shared__ float bc[2];
    const int row = blockIdx.x;
    const int tid = threadIdx.x;
    const int lane = tid & 31, wid = tid >> 5;

    float v[3];
    float s1 = 0.f;
#pragma unroll
    for (int t = 0; t < 3; t++) {
        v[t] = in[(size_t)row * D_MODEL + tid + t * 256];
        s1 += v[t];
    }
#pragma unroll
    for (int off = 16; off >= 1; off >>= 1) s1 += __shfl_xor_sync(0xffffffffu, s1, off);
    if (lane == 0) red[wid] = s1;
    __syncthreads();
    if (tid == 0) {
        float acc = 0.f;
        for (int w = 0; w < 8; w++) acc += red[w];
        bc[0] = acc / (float)D_MODEL;
    }
    __syncthreads();
    float mean = bc[0];

    float s2 = 0.f;
#pragma unroll
    for (int t = 0; t < 3; t++) {
        float d = v[t] - mean;
        s2 += d * d;
    }
#pragma unroll
    for (int off = 16; off >= 1; off >>= 1) s2 += __shfl_xor_sync(0xffffffffu, s2, off);
    if (lane == 0) red[wid] = s2;
    __syncthreads();
    if (tid == 0) {
        float acc = 0.f;
        for (int w = 0; w < 8; w++) acc += red[w];
        float var = acc / (float)(D_MODEL - 1);
        bc[1] = 1.f / (sqrtf(var) + LN_EPS);
    }
    __syncthreads();
    float inv = bc[1];

#pragma unroll
    for (int t = 0; t < 3; t++) {
        int c = tid + t * 256;
        float y = gamma[c] * (v[t] - mean) * inv + beta[c];
        out[(size_t)row * D_MODEL + c] = y;
        if (outH) outH[(size_t)row * D_MODEL + c] = __float2half(y);
    }
}

// ---------------- launch ----------------
extern "C" void kernel_launch(void* const* d_in, const int* in_sizes, int n_in,
                              void* d_out, int out_size)
{
    const float* x   = (const float*)d_in[0];
    const void*  mraw = (const void*)d_in[1];
    const float* wq = (const float*)d_in[2];
    const float* bq = (const float*)d_in[3];
    const float* wk = (const float*)d_in[4];
    const float* bk = (const float*)d_in[5];
    const float* wv = (const float*)d_in[6];
    const float* bv = (const float*)d_in[7];
    const float* wo = (const float*)d_in[8];
    const float* bo = (const float*)d_in[9];
    const float* w1 = (const float*)d_in[10];
    const float* b1 = (const float*)d_in[11];
    const float* w2 = (const float*)d_in[12];
    const float* b2 = (const float*)d_in[13];
    const float* g1 = (const float*)d_in[14];
    const float* be1 = (const float*)d_in[15];
    const float* g2 = (const float*)d_in[16];
    const float* be2 = (const float*)d_in[17];
    float* outp = (float*)d_out;

    __half *xh, *wqkvh, *woh, *w1h, *w2h, *qh, *kh, *vh, *ah, *ffh, *x1h;
    float *res1, *x1, *res2;
    cudaGetSymbolAddress((void**)&xh,    g_xh);
    cudaGetSymbolAddress((void**)&wqkvh, g_wqkvh);
    cudaGetSymbolAddress((void**)&woh,   g_woh);
    cudaGetSymbolAddress((void**)&w1h,   g_w1h);
    cudaGetSymbolAddress((void**)&w2h,   g_w2h);
    cudaGetSymbolAddress((void**)&qh,    g_qh);
    cudaGetSymbolAddress((void**)&kh,    g_kh);
    cudaGetSymbolAddress((void**)&vh,    g_vh);
    cudaGetSymbolAddress((void**)&ah,    g_ah);
    cudaGetSymbolAddress((void**)&ffh,   g_ffh);
    cudaGetSymbolAddress((void**)&x1h,   g_x1h);
    cudaGetSymbolAddress((void**)&res1,  g_res1);
    cudaGetSymbolAddress((void**)&x1,    g_x1);
    cudaGetSymbolAddress((void**)&res2,  g_res2);

    const int GSM = 2 * GBUF;        // 40960
    const int ASM = 2 * F_BUF;       // 37376
    cudaFuncSetAttribute((const void*)gemm_mma<EPI_QKV>,  cudaFuncAttributeMaxDynamicSharedMemorySize, GSM);
    cudaFuncSetAttribute((const void*)gemm_mma<EPI_ORES>, cudaFuncAttributeMaxDynamicSharedMemorySize, GSM);
    cudaFuncSetAttribute((const void*)gemm_mma<EPI_FF1>,  cudaFuncAttributeMaxDynamicSharedMemorySize, GSM);
    cudaFuncSetAttribute((const void*)gemm_mma<EPI_FF2>,  cudaFuncAttributeMaxDynamicSharedMemorySize, GSM);
    cudaFuncSetAttribute((const void*)flash_mma, cudaFuncAttributeMaxDynamicSharedMemorySize, ASM);

    dim3 blk(256);

    // 1 launch: all converts + mask
    megacvt<<<9985, blk>>>(x, wq, wk, wv, wo, w1, w2, mraw);

    dim3 gQKV(MROWS / 128, 3 * D_MODEL / 128);   // (32, 18)
    dim3 gP(MROWS / 128, D_MODEL / 128);         // (32, 6)
    dim3 gF1(MROWS / 128, DFF / 128);            // (32, 24)

    // merged QKV projection: Q (scaled), K, V — all fp16
    gemm_mma<EPI_QKV><<<gQKV, blk, GSM>>>(xh, wqkvh,
        bq, bk, bv, nullptr, nullptr, qh, kh, vh, D_MODEL, 3 * D_MODEL);

    // attention
    flash_mma<<<dim3(SEQ / 128, BHTOT), blk, ASM>>>(qh, kh, vh, ah);

    // O projection + residual(x) → res1; LN1 → x1 (fp32 + fp16)
    gemm_mma<EPI_ORES><<<gP, blk, GSM>>>(ah, woh,
        bo, nullptr, nullptr, x, res1, nullptr, nullptr, nullptr, D_MODEL, D_MODEL);
    layernorm_kernel<<<MROWS, blk>>>(res1, g1, be1, x1, x1h);

    // FFN (fp16 single-pass)
    gemm_mma<EPI_FF1><<<gF1, blk, GSM>>>(x1h, w1h,
        b1, nullptr, nullptr, nullptr, nullptr, ffh, nullptr, nullptr, D_MODEL, DFF);
    gemm_mma<EPI_FF2><<<gP, blk, GSM>>>(ffh, w2h,
        b2, nullptr, nullptr, x1, res2, nullptr, nullptr, nullptr, DFF, D_MODEL);
    layernorm_kernel<<<MROWS, blk>>>(res2, g2, be2, outp, nullptr);
}

// round 17
// speedup vs baseline: 10.5761x; 1.0219x over previous
#include <cuda_runtime.h>
#include <cuda_bf16.h>
#include <cuda_fp16.h>

#define D_MODEL 768
#define NHEADS  12
#define DKH     64
#define SEQ     2048
#define BATCH   2
#define DFF     3072
#define MROWS   (BATCH*SEQ)          // 4096
#define BHTOT   (BATCH*NHEADS)       // 24
#define LN_EPS  1e-6f
#define QSCL    0.180336880111f      // 0.125 * log2(e)
#define MADDC   (-1.8033688e8f)      // -1e9 * QSCL (additive mask, exp2 domain)

typedef __nv_bfloat16 bf16;
typedef __nv_bfloat162 bf162;

// ---------------- scratch (static device memory, allowed) ----------------
__device__ __align__(16) __half g_xh   [MROWS*D_MODEL];
__device__ __align__(16) __half g_wqkvh[3*D_MODEL*D_MODEL];
__device__ __align__(16) __half g_woh  [D_MODEL*D_MODEL];
__device__ __align__(16) __half g_w1h  [DFF*D_MODEL];
__device__ __align__(16) __half g_w2h  [D_MODEL*DFF];
__device__ __align__(16) __half g_qh   [BHTOT*SEQ*DKH];
__device__ __align__(16) __half g_kh   [BHTOT*SEQ*DKH];
__device__ __align__(16) __half g_vh   [BHTOT*SEQ*DKH];
__device__ __align__(16) __half g_ah   [MROWS*D_MODEL];
__device__ __align__(16) __half g_ffh  [MROWS*DFF];
__device__ __align__(16) __half g_x1h  [MROWS*D_MODEL];
__device__ __align__(16) float g_res1[MROWS*D_MODEL];
__device__ __align__(16) float g_x1  [MROWS*D_MODEL];
__device__ __align__(16) float g_res2[MROWS*D_MODEL];
__device__ __align__(16) float g_maskf[BATCH*SEQ];   // additive: 0.0 keep, MADDC masked

// ---------------- asm helpers ----------------
__device__ __forceinline__ void ldsm4(unsigned* r, unsigned addr) {
    asm volatile("ldmatrix.sync.aligned.m8n8.x4.shared.b16 {%0,%1,%2,%3}, [%4];"
        : "=r"(r[0]), "=r"(r[1]), "=r"(r[2]), "=r"(r[3]) : "r"(addr));
}
__device__ __forceinline__ void ldsm4t(unsigned* r, unsigned addr) {
    asm volatile("ldmatrix.sync.aligned.m8n8.x4.trans.shared.b16 {%0,%1,%2,%3}, [%4];"
        : "=r"(r[0]), "=r"(r[1]), "=r"(r[2]), "=r"(r[3]) : "r"(addr));
}
__device__ __forceinline__ void mma16816h(float* c, const unsigned* a, unsigned b0, unsigned b1) {
    asm volatile("mma.sync.aligned.m16n8k16.row.col.f32.f16.f16.f32 "
        "{%0,%1,%2,%3}, {%4,%5,%6,%7}, {%8,%9}, {%0,%1,%2,%3};"
        : "+f"(c[0]), "+f"(c[1]), "+f"(c[2]), "+f"(c[3])
        : "r"(a[0]), "r"(a[1]), "r"(a[2]), "r"(a[3]), "r"(b0), "r"(b1));
}
__device__ __forceinline__ void cp16(unsigned saddr, const void* gptr) {
    asm volatile("cp.async.ca.shared.global [%0], [%1], 16;" :: "r"(saddr), "l"(gptr));
}
__device__ __forceinline__ void cp_commit() { asm volatile("cp.async.commit_group;"); }
__device__ __forceinline__ void cp_wait2() { asm volatile("cp.async.wait_group 2;"); }
__device__ __forceinline__ void cp_wait1() { asm volatile("cp.async.wait_group 1;"); }
__device__ __forceinline__ void cp_wait0() { asm volatile("cp.async.wait_group 0;"); }

__device__ __forceinline__ unsigned pkhf(float a, float b) {
    __half2 t = __floats2half2_rn(a, b);
    return reinterpret_cast<unsigned&>(t);
}
__device__ __forceinline__ unsigned long long pk2d(float lo, float hi) {
    unsigned long long r;
    asm("mov.b64 %0, {%1,%2};" : "=l"(r) : "f"(lo), "f"(hi));
    return r;
}
#define MULX2(d, a, b) asm("mul.rn.f32x2 %0, %1, %2;" : "=l"(d) : "l"(a), "l"(b))

// ---------------- mega convert (mask + all weight/input converts, 1 launch) ----
__device__ __forceinline__ void cvt_h(const float* s, __half* h, int lb, int tid) {
    int i = (lb * 256 + tid) * 4;
    float4 v = *(const float4*)(s + i);
    *(unsigned*)(h + i)     = pkhf(v.x, v.y);
    *(unsigned*)(h + i + 2) = pkhf(v.z, v.w);
}

__global__ __launch_bounds__(256)
void megacvt(const float* __restrict__ x, const float* __restrict__ wq,
             const float* __restrict__ wk, const float* __restrict__ wv,
             const float* __restrict__ wo, const float* __restrict__ w1,
             const float* __restrict__ w2, const void* __restrict__ mraw)
{
    const int b = blockIdx.x, tid = threadIdx.x;
    const int WSZ = D_MODEL * D_MODEL;           // 589824
    if (b < 3072)      cvt_h(x,  g_xh, b, tid);
    else if (b < 3648) cvt_h(wq, g_wqkvh,           b - 3072, tid);
    else if (b < 4224) cvt_h(wk, g_wqkvh + WSZ,     b - 3648, tid);
    else if (b < 4800) cvt_h(wv, g_wqkvh + 2 * WSZ, b - 4224, tid);
    else if (b < 5376) cvt_h(wo, g_woh, b - 4800, tid);
    else if (b < 7680) cvt_h(w1, g_w1h, b - 5376, tid);
    else if (b < 9984) cvt_h(w2, g_w2h, b - 7680, tid);
    else {
        // mask canonicalization (single block): detect int32 vs uint8, write additive floats
        __shared__ int s_flag;
        const unsigned int* w = (const unsigned int*)mraw;
        if (tid == 0) s_flag = 0;
        __syncthreads();
        int any = 0;
        for (int i = tid; i < 1024; i += 256)
            if (w[i] > 1u) any = 1;
        if (any) atomicOr(&s_flag, 1);
        __syncthreads();
        if (s_flag) {
            const unsigned char* mb = (const unsigned char*)mraw;
            for (int i = tid; i < BATCH * SEQ; i += 256)
                g_maskf[i] = mb[i] ? MADDC : 0.0f;
        } else {
            const int* mi = (const int*)mraw;
            for (int i = tid; i < BATCH * SEQ; i += 256)
                g_maskf[i] = mi[i] ? MADDC : 0.0f;
        }
    }
}

// ---------------- tensor-core GEMM (fp16): C = A @ W^T ------------
// block (64*MI)x128, ktile 32, 8 warps (warp tile 16*MI m x 64 n).
// 4-stage cp.async pipeline, ONE __syncthreads per ktile.
enum { EPI_QKV = 0, EPI_ORES = 1, EPI_FF1 = 2, EPI_FF2 = 3 };

template<int EPI, int MI>
__global__ __launch_bounds__(256, 2)
void gemm_mma(const __half* __restrict__ Ah, const __half* __restrict__ Wh,
              const float* __restrict__ bias, const float* __restrict__ bias2,
              const float* __restrict__ bias3, const float* __restrict__ res,
              float* __restrict__ outF, __half* __restrict__ outQ,
              __half* __restrict__ outK, __half* __restrict__ outV,
              int Kdim, int Ndim)
{
    const int AOFF  = MI * 5120;          // A region bytes (rows*80)
    const int BUFSZ = AOFF + 10240;       // + W region (128 rows * 80)
    const int MT    = 64 * MI;            // CTA m-tile

    extern __shared__ char smem[];
    const unsigned sb = (unsigned)__cvta_generic_to_shared(smem);
    const int tid = threadIdx.x, lane = tid & 31, warp = tid >> 5;
    const int wm = warp & 3, wn = warp >> 2;
    const int m0 = blockIdx.x * MT, n0 = blockIdx.y * 128;

    // loaders
    const int lrW = tid >> 1, lcW = (tid & 1) * 2;
    const __half* gW = Wh + (size_t)(n0 + lrW) * Kdim + lcW * 8;
    const unsigned stW = lrW * 80 + lcW * 16;
    // A loader: MI=2 -> 2 chunks like W; MI=1 -> 64 rows, 1 chunk/thread
    const int lrA = (MI == 2) ? (tid >> 1) : (tid >> 2);
    const int lcA = (MI == 2) ? ((tid & 1) * 2) : (tid & 3);
    const __half* gA = Ah + (size_t)(m0 + lrA) * Kdim + lcA * 8;
    const unsigned stA = lrA * 80 + lcA * 16;

    float acc[MI][8][4] = {};
    const int nk = Kdim / 32;

    auto issue = [&](int kt, int buf) {
        unsigned b = sb + buf * BUFSZ;
        int ke = kt * 32;
        if (MI == 2) {
#pragma unroll
            for (int c = 0; c < 2; c++)
                cp16(b + stA + c * 16, gA + ke + c * 8);
        } else {
            cp16(b + stA, gA + ke);
        }
#pragma unroll
        for (int c = 0; c < 2; c++)
            cp16(b + AOFF + stW + c * 16, gW + ke + c * 8);
        cp_commit();
    };

    issue(0, 0); issue(1, 1); issue(2, 2);

    for (int kt = 0; kt < nk; kt++) {
        int buf = kt & 3;
        int rem = nk - 1 - kt;
        if (rem >= 2) cp_wait2(); else if (rem == 1) cp_wait1(); else cp_wait0();
        __syncthreads();

        unsigned b = sb + buf * BUFSZ;
        const unsigned ar = lane & 15;
#pragma unroll
        for (int ks = 0; ks < 2; ks++) {
            const unsigned ac = ks * 2 + (lane >> 4);
            unsigned ah[MI][4];
#pragma unroll
            for (int mi = 0; mi < MI; mi++)
                ldsm4(ah[mi], b + (wm * (16 * MI) + mi * 16 + ar) * 80 + ac * 16);
#pragma unroll
            for (int ni2 = 0; ni2 < 4; ni2++) {
                unsigned bh[4];
                ldsm4(bh, b + AOFF + (wn * 64 + ni2 * 16 + ar) * 80 + ac * 16);
#pragma unroll
                for (int mi = 0; mi < MI; mi++) {
                    mma16816h(acc[mi][ni2 * 2],     ah[mi], bh[0], bh[2]);
                    mma16816h(acc[mi][ni2 * 2 + 1], ah[mi], bh[1], bh[3]);
                }
            }
        }
        if (kt + 3 < nk) issue(kt + 3, (kt + 3) & 3);
    }

    // epilogue
    const int sec = (EPI == EPI_QKV) ? (n0 / D_MODEL) : 0;   // 0=Q 1=K 2=V
    const float* bs = (EPI == EPI_QKV)
        ? (sec == 0 ? bias : (sec == 1 ? bias2 : bias3)) : bias;
#pragma unroll
    for (int mi = 0; mi < MI; mi++)
#pragma unroll
    for (int rr = 0; rr < 2; rr++) {
        int m = m0 + wm * (16 * MI) + mi * 16 + (lane >> 2) + rr * 8;
#pragma unroll
        for (int ni = 0; ni < 8; ni++) {
            int n = n0 + wn * 64 + ni * 8 + (lane & 3) * 2;
            float a0 = acc[mi][ni][rr * 2 + 0];
            float a1 = acc[mi][ni][rr * 2 + 1];
            if (EPI == EPI_QKV) {
                int nl = n - sec * D_MODEL;
                float v0 = a0 + bs[nl], v1 = a1 + bs[nl + 1];
                int b_ = m >> 11, s_ = m & (SEQ - 1);
                int h_ = nl >> 6, d_ = nl & 63;
                size_t idx = ((size_t)(b_ * NHEADS + h_) * SEQ + s_) * DKH + d_;
                if (sec == 0)      *(unsigned*)(outQ + idx) = pkhf(v0 * QSCL, v1 * QSCL);
                else if (sec == 1) *(unsigned*)(outK + idx) = pkhf(v0, v1);
                else               *(unsigned*)(outV + idx) = pkhf(v0, v1);
            } else if (EPI == EPI_ORES || EPI == EPI_FF2) {
                float v0 = a0 + bs[n] + res[(size_t)m * Ndim + n];
                float v1 = a1 + bs[n + 1] + res[(size_t)m * Ndim + n + 1];
                outF[(size_t)m * Ndim + n]     = v0;
                outF[(size_t)m * Ndim + n + 1] = v1;
            } else { // EPI_FF1: relu, fp16 out
                float v0 = fmaxf(a0 + bs[n], 0.f);
                float v1 = fmaxf(a1 + bs[n + 1], 0.f);
                *(unsigned*)(outQ + (size_t)m * Ndim + n) = pkhf(v0, v1);
            }
        }
    }
}

// ---------------- flash attention: fp16 QK^T, f16x2-exp softmax, f16 PV -------
// 3-stage cp.async pipeline, ONE __syncthreads per K-tile.
#define FK 0
#define FV 9216
#define FM 18432
#define F_BUF 18688

__global__ __launch_bounds__(256)
void flash_mma(const __half* __restrict__ qm, const __half* __restrict__ km,
               const __half* __restrict__ vm, __half* __restrict__ ao)
{
    extern __shared__ char smem[];
    const unsigned sb = (unsigned)__cvta_generic_to_shared(smem);
    const int tid = threadIdx.x, lane = tid & 31, w = tid >> 5;
    const int bh = blockIdx.y;
    const int b_ = bh / NHEADS, h_ = bh % NHEADS;
    const int q0 = blockIdx.x * 128;

    unsigned qf[4][4];
    {
        int r = tid >> 2, cbq = (tid & 3) * 2;
#pragma unroll
        for (int p = 0; p < 2; p++) {
            const __half* gq = qm + ((size_t)bh * SEQ + q0 + p * 64 + r) * DKH + cbq * 8;
            uint4 h0 = *(const uint4*)gq;
            uint4 h1 = *(const uint4*)(gq + 8);
            __syncthreads();
            *(uint4*)(smem + FK + r * 144 + cbq * 16)      = h0;
            *(uint4*)(smem + FK + r * 144 + cbq * 16 + 16) = h1;
            __syncthreads();
            if ((w >> 2) == p) {
                int lrow = (w - p * 4) * 16 + (lane & 15);
#pragma unroll
                for (int ks = 0; ks < 4; ks++) {
                    unsigned addr = sb + FK + lrow * 144 + (ks * 2 + (lane >> 4)) * 16;
                    ldsm4(qf[ks], addr);
                }
            }
        }
        __syncthreads();
    }

    const int r = tid >> 2, cb = (tid & 3) * 2;
    const __half* gK = km + ((size_t)bh * SEQ + r) * DKH + cb * 8;
    const __half* gV = vm + ((size_t)bh * SEQ + r) * DKH + cb * 8;
    const float* gM = g_maskf + b_ * SEQ;
    const unsigned st = r * 144 + cb * 16;

    auto issue = [&](int kt, int buf) {
        unsigned base = sb + buf * F_BUF;
        size_t ke = (size_t)kt * 64 * DKH;
#pragma unroll
        for (int c = 0; c < 2; c++) {
            cp16(base + FK + st + c * 16, gK + ke + c * 8);
            cp16(base + FV + st + c * 16, gV + ke + c * 8);
        }
        if (tid < 16) cp16(base + FM + tid * 16, gM + kt * 64 + tid * 4);
        cp_commit();
    };

    __align__(16) float o[8][4] = {};
    float mi[2] = {-1e30f, -1e30f};
    float li[2] = {0.f, 0.f};

    issue(0, 0); issue(1, 1);
    const int NT = SEQ / 64;
    for (int kt = 0; kt < NT; kt++) {
        int buf = kt % 3;
        unsigned base = sb + buf * F_BUF;
        if (kt + 1 < NT) cp_wait1(); else cp_wait0();
        __syncthreads();

        // S = Q K^T (exp2-domain: Q pre-scaled by 0.125*log2e)
        float s[8][4] = {};
        const unsigned ar = lane & 15;
#pragma unroll
        for (int ks = 0; ks < 4; ks++) {
            const unsigned ac = ks * 2 + (lane >> 4);
#pragma unroll
            for (int ni2 = 0; ni2 < 4; ni2++) {
                unsigned kr[4];
                ldsm4(kr, base + FK + (ni2 * 16 + ar) * 144 + ac * 16);
                mma16816h(s[ni2 * 2],     qf[ks], kr[0], kr[2]);
                mma16816h(s[ni2 * 2 + 1], qf[ks], kr[1], kr[3]);
            }
        }

        // additive mask (0 or -1.8e8) for this thread's 16 columns
        const float* msk = (const float*)(smem + buf * F_BUF + FM);
        float madd[16];
#pragma unroll
        for (int ni = 0; ni < 8; ni++) {
            int col = ni * 8 + (lane & 3) * 2;
            madd[ni * 2]     = msk[col];
            madd[ni * 2 + 1] = msk[col + 1];
        }

        unsigned pf[8][2];   // P fragments as f16x2, [ni][rr]
#pragma unroll
        for (int rr = 0; rr < 2; rr++) {
            float rmax = -1e30f;
#pragma unroll
            for (int ni = 0; ni < 8; ni++)
#pragma unroll
                for (int jj = 0; jj < 2; jj++) {
                    float xx = s[ni][rr * 2 + jj] + madd[ni * 2 + jj];
                    s[ni][rr * 2 + jj] = xx;
                    rmax = fmaxf(rmax, xx);
                }
            rmax = fmaxf(rmax, __shfl_xor_sync(0xffffffffu, rmax, 1));
            rmax = fmaxf(rmax, __shfl_xor_sync(0xffffffffu, rmax, 2));
            float mnew = fmaxf(mi[rr], rmax);
            float fac = exp2f(mi[rr] - mnew);
            float rsum = 0.f;
#pragma unroll
            for (int ni = 0; ni < 8; ni++) {
                unsigned hp = pkhf(s[ni][rr * 2] - mnew, s[ni][rr * 2 + 1] - mnew);
                unsigned pe;
                asm("ex2.approx.f16x2 %0, %1;" : "=r"(pe) : "r"(hp));
                pf[ni][rr] = pe;
                __half2 pv = reinterpret_cast<__half2&>(pe);
                float2 pg = __half22float2(pv);
                rsum += pg.x + pg.y;
            }
            rsum += __shfl_xor_sync(0xffffffffu, rsum, 1);
            rsum += __shfl_xor_sync(0xffffffffu, rsum, 2);
            li[rr] = li[rr] * fac + rsum;
            mi[rr] = mnew;
            unsigned long long fp = pk2d(fac, fac);
            unsigned long long* op = (unsigned long long*)o;
#pragma unroll
            for (int dj = 0; dj < 8; dj++)
                MULX2(op[dj * 2 + rr], op[dj * 2 + rr], fp);
        }

        // O += P V (f16 x f16)
#pragma unroll
        for (int kk = 0; kk < 4; kk++) {
            unsigned ph[4] = { pf[2 * kk][0], pf[2 * kk][1],
                               pf[2 * kk + 1][0], pf[2 * kk + 1][1] };
            int g = lane >> 3;
            int vrow = kk * 16 + (g & 1) * 8 + (lane & 7);
#pragma unroll
            for (int dj2 = 0; dj2 < 4; dj2++) {
                int dcol = dj2 * 16 + (g >> 1) * 8;
                unsigned vr[4];
                ldsm4t(vr, base + FV + vrow * 144 + dcol * 2);
                mma16816h(o[dj2 * 2],     ph, vr[0], vr[1]);
                mma16816h(o[dj2 * 2 + 1], ph, vr[2], vr[3]);
            }
        }
        if (kt + 2 < NT) issue(kt + 2, (kt + 2) % 3);
    }

#pragma unroll
    for (int rr = 0; rr < 2; rr++) {
        int qrow = q0 + w * 16 + (lane >> 2) + rr * 8;
        float inv = 1.f / li[rr];
        size_t rowoff = ((size_t)(b_ * SEQ + qrow)) * D_MODEL + h_ * DKH;
#pragma unroll
        for (int dj = 0; dj < 8; dj++) {
            int d = dj * 8 + (lane & 3) * 2;
            *(unsigned*)(ao + rowoff + d) =
                pkhf(o[dj][rr * 2] * inv, o[dj][rr * 2 + 1] * inv);
        }
    }
}

// ---------------- LayerNorm (torch semantics: ddof=1, /(std+eps)) ----------------
__global__ __launch_bounds__(256)
void layernorm_kernel(const float* __restrict__ in, const float* __restrict__ gamma,
                      const float* __restrict__ beta, float* __restrict__ out,
                      __half* __restrict__ outH)
{
    __shared__ float red[32];
    __shared__ float bc[2];
    const int row = blockIdx.x;
    const int tid = threadIdx.x;
    const int lane = tid & 31, wid = tid >> 5;

    float v[3];
    float s1 = 0.f;
#pragma unroll
    for (int t = 0; t < 3; t++) {
        v[t] = in[(size_t)row * D_MODEL + tid + t * 256];
        s1 += v[t];
    }
#pragma unroll
    for (int off = 16; off >= 1; off >>= 1) s1 += __shfl_xor_sync(0xffffffffu, s1, off);
    if (lane == 0) red[wid] = s1;
    __syncthreads();
    if (tid == 0) {
        float acc = 0.f;
        for (int w = 0; w < 8; w++) acc += red[w];
        bc[0] = acc / (float)D_MODEL;
    }
    __syncthreads();
    float mean = bc[0];

    float s2 = 0.f;
#pragma unroll
    for (int t = 0; t < 3; t++) {
        float d = v[t] - mean;
        s2 += d * d;
    }
#pragma unroll
    for (int off = 16; off >= 1; off >>= 1) s2 += __shfl_xor_sync(0xffffffffu, s2, off);
    if (lane == 0) red[wid] = s2;
    __syncthreads();
    if (tid == 0) {
        float acc = 0.f;
        for (int w = 0; w < 8; w++) acc += red[w];
        float var = acc / (float)(D_MODEL - 1);
        bc[1] = 1.f / (sqrtf(var) + LN_EPS);
    }
    __syncthreads();
    float inv = bc[1];

#pragma unroll
    for (int t = 0; t < 3; t++) {
        int c = tid + t * 256;
        float y = gamma[c] * (v[t] - mean) * inv + beta[c];
        out[(size_t)row * D_MODEL + c] = y;
        if (outH) outH[(size_t)row * D_MODEL + c] = __float2half(y);
    }
}

// ---------------- launch ----------------
extern "C" void kernel_launch(void* const* d_in, const int* in_sizes, int n_in,
                              void* d_out, int out_size)
{
    const float* x   = (const float*)d_in[0];
    const void*  mraw = (const void*)d_in[1];
    const float* wq = (const float*)d_in[2];
    const float* bq = (const float*)d_in[3];
    const float* wk = (const float*)d_in[4];
    const float* bk = (const float*)d_in[5];
    const float* wv = (const float*)d_in[6];
    const float* bv = (const float*)d_in[7];
    const float* wo = (const float*)d_in[8];
    const float* bo = (const float*)d_in[9];
    const float* w1 = (const float*)d_in[10];
    const float* b1 = (const float*)d_in[11];
    const float* w2 = (const float*)d_in[12];
    const float* b2 = (const float*)d_in[13];
    const float* g1 = (const float*)d_in[14];
    const float* be1 = (const float*)d_in[15];
    const float* g2 = (const float*)d_in[16];
    const float* be2 = (const float*)d_in[17];
    float* outp = (float*)d_out;

    __half *xh, *wqkvh, *woh, *w1h, *w2h, *qh, *kh, *vh, *ah, *ffh, *x1h;
    float *res1, *x1, *res2;
    cudaGetSymbolAddress((void**)&xh,    g_xh);
    cudaGetSymbolAddress((void**)&wqkvh, g_wqkvh);
    cudaGetSymbolAddress((void**)&woh,   g_woh);
    cudaGetSymbolAddress((void**)&w1h,   g_w1h);
    cudaGetSymbolAddress((void**)&w2h,   g_w2h);
    cudaGetSymbolAddress((void**)&qh,    g_qh);
    cudaGetSymbolAddress((void**)&kh,    g_kh);
    cudaGetSymbolAddress((void**)&vh,    g_vh);
    cudaGetSymbolAddress((void**)&ah,    g_ah);
    cudaGetSymbolAddress((void**)&ffh,   g_ffh);
    cudaGetSymbolAddress((void**)&x1h,   g_x1h);
    cudaGetSymbolAddress((void**)&res1,  g_res1);
    cudaGetSymbolAddress((void**)&x1,    g_x1);
    cudaGetSymbolAddress((void**)&res2,  g_res2);

    const int GSM2 = 4 * 20480;      // 81920 (MI=2, 4-stage)
    const int GSM1 = 4 * 15360;      // 61440 (MI=1, 4-stage)
    const int ASM  = 3 * F_BUF;      // 56064 (3-stage)
    cudaFuncSetAttribute((const void*)gemm_mma<EPI_QKV, 2>,  cudaFuncAttributeMaxDynamicSharedMemorySize, GSM2);
    cudaFuncSetAttribute((const void*)gemm_mma<EPI_FF1, 2>,  cudaFuncAttributeMaxDynamicSharedMemorySize, GSM2);
    cudaFuncSetAttribute((const void*)gemm_mma<EPI_ORES, 1>, cudaFuncAttributeMaxDynamicSharedMemorySize, GSM1);
    cudaFuncSetAttribute((const void*)gemm_mma<EPI_FF2, 1>,  cudaFuncAttributeMaxDynamicSharedMemorySize, GSM1);
    cudaFuncSetAttribute((const void*)flash_mma, cudaFuncAttributeMaxDynamicSharedMemorySize, ASM);

    dim3 blk(256);

    // 1 launch: all converts + mask
    megacvt<<<9985, blk>>>(x, wq, wk, wv, wo, w1, w2, mraw);

    dim3 gQKV(MROWS / 128, 3 * D_MODEL / 128);   // (32, 18)
    dim3 gP64(MROWS / 64, D_MODEL / 128);        // (64, 6)  MI=1 tiles
    dim3 gF1(MROWS / 128, DFF / 128);            // (32, 24)

    // merged QKV projection: Q (scaled), K, V — all fp16
    gemm_mma<EPI_QKV, 2><<<gQKV, blk, GSM2>>>(xh, wqkvh,
        bq, bk, bv, nullptr, nullptr, qh, kh, vh, D_MODEL, 3 * D_MODEL);

    // attention
    flash_mma<<<dim3(SEQ / 128, BHTOT), blk, ASM>>>(qh, kh, vh, ah);

    // O projection + residual(x) → res1; LN1 → x1 (fp32 + fp16)
    gemm_mma<EPI_ORES, 1><<<gP64, blk, GSM1>>>(ah, woh,
        bo, nullptr, nullptr, x, res1, nullptr, nullptr, nullptr, D_MODEL, D_MODEL);
    layernorm_kernel<<<MROWS, blk>>>(res1, g1, be1, x1, x1h);

    // FFN (fp16 single-pass)
    gemm_mma<EPI_FF1, 2><<<gF1, blk, GSM2>>>(x1h, w1h,
        b1, nullptr, nullptr, nullptr, nullptr, ffh, nullptr, nullptr, D_MODEL, DFF);
    gemm_mma<EPI_FF2, 1><<<gP64, blk, GSM1>>>(ffh, w2h,
        b2, nullptr, nullptr, x1, res2, nullptr, nullptr, nullptr, DFF, D_MODEL);
    layernorm_kernel<<<MROWS, blk>>>(res2, g2, be2, outp, nullptr);
}